// round 1
// baseline (speedup 1.0000x reference)
#include <cuda_runtime.h>

#define N0   50000
#define NM   25000
#define DD   128
#define NE   800000
#define NE12 400000

// ---------------- static device scratch (no runtime allocation) ----------------
__device__ float g_net1[NM * DD];            // net1: shared first hop (path 1)
__device__ float g_mid [NM * DD];            // reused: net2, net3, long-path m2/n2
__device__ float g_n3b [NM * DD];            // long-path m3/n3
__device__ float g_sum [N0 * DD];            // reused N0-target sum buffer (x5)
__device__ float g_allm[(long long)N0 * 5 * DD];  // [n][p][d] post-linear features

__device__ int g_c_e1s[N0], g_c_e2s[N0], g_c_e3s[N0];
__device__ int g_c_e1d[NM], g_c_e2d[NM], g_c_e3d[NM];
__device__ int g_c_e12d[NM], g_c_e12s[NM], g_c_e13d[NM], g_c_e13s[NM];

// ---------------- kernels ----------------

__global__ void k_zero_counts() {
    int i = blockIdx.x * blockDim.x + threadIdx.x;
    if (i < N0) { g_c_e1s[i] = 0; g_c_e2s[i] = 0; g_c_e3s[i] = 0; }
    if (i < NM) {
        g_c_e1d[i] = 0; g_c_e2d[i] = 0; g_c_e3d[i] = 0;
        g_c_e12d[i] = 0; g_c_e12s[i] = 0; g_c_e13d[i] = 0; g_c_e13s[i] = 0;
    }
}

__global__ void k_count(const int* __restrict__ e1s, const int* __restrict__ e1d,
                        const int* __restrict__ e2s, const int* __restrict__ e2d,
                        const int* __restrict__ e3s, const int* __restrict__ e3d,
                        const int* __restrict__ e12s, const int* __restrict__ e12d,
                        const int* __restrict__ e13s, const int* __restrict__ e13d) {
    int i = blockIdx.x * blockDim.x + threadIdx.x;
    if (i < NE) {
        atomicAdd(&g_c_e1s[e1s[i]], 1); atomicAdd(&g_c_e1d[e1d[i]], 1);
        atomicAdd(&g_c_e2s[e2s[i]], 1); atomicAdd(&g_c_e2d[e2d[i]], 1);
        atomicAdd(&g_c_e3s[e3s[i]], 1); atomicAdd(&g_c_e3d[e3d[i]], 1);
    }
    if (i < NE12) {
        atomicAdd(&g_c_e12s[e12s[i]], 1); atomicAdd(&g_c_e12d[e12d[i]], 1);
        atomicAdd(&g_c_e13s[e13s[i]], 1); atomicAdd(&g_c_e13d[e13d[i]], 1);
    }
}

__global__ void k_zero_f(float4* __restrict__ p, int n4) {
    int i = blockIdx.x * blockDim.x + threadIdx.x;
    if (i < n4) p[i] = make_float4(0.f, 0.f, 0.f, 0.f);
}

// One warp per edge: gather feat[gidx[e]] (512B coalesced), optional per-edge
// weight, vectorized reduction into osum[sidx[e]].
__global__ void k_scatter(const float* __restrict__ feat,
                          const int* __restrict__ gidx,
                          const int* __restrict__ sidx,
                          const float* __restrict__ w,
                          float* __restrict__ osum, int ne) {
    int gt = blockIdx.x * blockDim.x + threadIdx.x;
    int e = gt >> 5;
    int lane = gt & 31;
    if (e >= ne) return;
    int g = __ldg(gidx + e);
    int s = __ldg(sidx + e);
    float4 v = __ldg((const float4*)(feat + (long long)g * DD) + lane);
    if (w) {
        float ww = __ldg(w + e);
        v.x *= ww; v.y *= ww; v.z *= ww; v.w *= ww;
    }
    float* dst = osum + (long long)s * DD + lane * 4;
    asm volatile("red.global.add.v4.f32 [%0], {%1,%2,%3,%4};"
                 :: "l"(dst), "f"(v.x), "f"(v.y), "f"(v.z), "f"(v.w)
                 : "memory");
}

// net = (sum / max(cnt,1) + xm) * 0.5, in place over nrow x 128
__global__ void k_finmid(float* __restrict__ sum, const int* __restrict__ cnt,
                         const float* __restrict__ xm, int nrow) {
    int i = blockIdx.x * blockDim.x + threadIdx.x;  // float4 index
    int n4 = nrow * (DD / 4);
    if (i >= n4) return;
    int row = i >> 5;
    int c = __ldg(cnt + row); if (c < 1) c = 1;
    float r = 1.0f / (float)c;
    float4 s = ((float4*)sum)[i];
    float4 x = __ldg((const float4*)xm + i);
    s.x = (s.x * r + x.x) * 0.5f;
    s.y = (s.y * r + x.y) * 0.5f;
    s.z = (s.z * r + x.z) * 0.5f;
    s.w = (s.w * r + x.w) * 0.5f;
    ((float4*)sum)[i] = s;
}

// out[n, p*128 + j] = relu( b[j] + sum_k (sin[n,k]/max(cnt[n],1)) * W[j,k] )
// 256 threads, 32 rows/block, W transposed in smem (pad 132), 4 rows/warp.
#define GEMM_SMEM ((DD * 132 + 32 * DD) * 4)
__global__ void k_gemm_relu(const float* __restrict__ sin,
                            const int* __restrict__ cnt,
                            const float* __restrict__ W,
                            const float* __restrict__ b,
                            float* __restrict__ obase) {
    extern __shared__ float sh[];
    float* Wt = sh;                 // 128 x 132 (Wt[k*132+j] = W[j,k])
    float* xs = sh + DD * 132;      // 32 x 128, pre-scaled by 1/count
    int tid = threadIdx.x;

    for (int idx = tid; idx < DD * DD; idx += 256) {
        int j = idx >> 7, k = idx & 127;
        Wt[k * 132 + j] = W[idx];
    }
    int row0 = blockIdx.x * 32;
    for (int idx = tid; idx < 32 * DD; idx += 256) {
        int r = idx >> 7, k = idx & 127;
        int row = row0 + r;
        float v = 0.f;
        if (row < N0) {
            int c = __ldg(cnt + row); if (c < 1) c = 1;
            v = __ldg(sin + (long long)row * DD + k) * (1.0f / (float)c);
        }
        xs[idx] = v;
    }
    __syncthreads();

    int warp = tid >> 5, lane = tid & 31;
    int r0 = warp * 4;
    float4 a0 = make_float4(0.f, 0.f, 0.f, 0.f);
    float4 a1 = a0, a2 = a0, a3 = a0;

    #pragma unroll 16
    for (int k = 0; k < DD; k++) {
        float4 wv = *(const float4*)(Wt + k * 132 + lane * 4);
        float x0 = xs[(r0 + 0) * DD + k];
        float x1 = xs[(r0 + 1) * DD + k];
        float x2 = xs[(r0 + 2) * DD + k];
        float x3 = xs[(r0 + 3) * DD + k];
        a0.x += wv.x * x0; a0.y += wv.y * x0; a0.z += wv.z * x0; a0.w += wv.w * x0;
        a1.x += wv.x * x1; a1.y += wv.y * x1; a1.z += wv.z * x1; a1.w += wv.w * x1;
        a2.x += wv.x * x2; a2.y += wv.y * x2; a2.z += wv.z * x2; a2.w += wv.w * x2;
        a3.x += wv.x * x3; a3.y += wv.y * x3; a3.z += wv.z * x3; a3.w += wv.w * x3;
    }

    float4 bb = __ldg((const float4*)(b) + lane);
    float4 accs[4] = {a0, a1, a2, a3};
    #pragma unroll
    for (int r = 0; r < 4; r++) {
        int row = row0 + r0 + r;
        if (row < N0) {
            float4 o;
            o.x = fmaxf(accs[r].x + bb.x, 0.f);
            o.y = fmaxf(accs[r].y + bb.y, 0.f);
            o.z = fmaxf(accs[r].z + bb.z, 0.f);
            o.w = fmaxf(accs[r].w + bb.w, 0.f);
            *(float4*)(obase + (long long)row * (5 * DD) + lane * 4) = o;
        }
    }
}

// one warp per node: 5 dots vs att_vec, softmax over 5, weighted combine
__global__ void k_att(const float* __restrict__ attv, float* __restrict__ out) {
    int gt = blockIdx.x * blockDim.x + threadIdx.x;
    int n = gt >> 5;
    int lane = gt & 31;
    if (n >= N0) return;
    const float4* base = (const float4*)(g_allm + (long long)n * (5 * DD));
    float4 a[5];
    float sc[5];
    #pragma unroll
    for (int p = 0; p < 5; p++) {
        a[p] = base[p * 32 + lane];
        float4 av = __ldg((const float4*)attv + p * 32 + lane);
        float d = a[p].x * av.x + a[p].y * av.y + a[p].z * av.z + a[p].w * av.w;
        #pragma unroll
        for (int o = 16; o; o >>= 1) d += __shfl_xor_sync(0xFFFFFFFFu, d, o);
        sc[p] = d;
    }
    float m = sc[0];
    #pragma unroll
    for (int p = 1; p < 5; p++) m = fmaxf(m, sc[p]);
    float ssum = 0.f;
    #pragma unroll
    for (int p = 0; p < 5; p++) { sc[p] = __expf(sc[p] - m); ssum += sc[p]; }
    float inv = 1.0f / ssum;
    float4 o = make_float4(0.f, 0.f, 0.f, 0.f);
    #pragma unroll
    for (int p = 0; p < 5; p++) {
        float wgt = sc[p] * inv;
        o.x += wgt * a[p].x; o.y += wgt * a[p].y;
        o.z += wgt * a[p].z; o.w += wgt * a[p].w;
    }
    ((float4*)out)[(long long)n * 32 + lane] = o;
}

// ---------------- host orchestration (graph-capturable: launches only) ----------------
extern "C" void kernel_launch(void* const* d_in, const int* in_sizes, int n_in,
                              void* d_out, int out_size) {
    const float* x_node = (const float*)d_in[0];
    const float* x1   = (const float*)d_in[1];
    const float* x2   = (const float*)d_in[2];
    const float* x3   = (const float*)d_in[3];
    const float* w1   = (const float*)d_in[4];
    const float* w2   = (const float*)d_in[5];
    const float* w3   = (const float*)d_in[6];
    const float* W1   = (const float*)d_in[7];
    const float* b1   = (const float*)d_in[8];
    const float* W2   = (const float*)d_in[9];
    const float* b2   = (const float*)d_in[10];
    const float* W3   = (const float*)d_in[11];
    const float* b3   = (const float*)d_in[12];
    const float* W121 = (const float*)d_in[13];
    const float* b121 = (const float*)d_in[14];
    const float* W131 = (const float*)d_in[15];
    const float* b131 = (const float*)d_in[16];
    const float* attv = (const float*)d_in[17];
    const int* e1s  = (const int*)d_in[18];
    const int* e1d  = (const int*)d_in[19];
    const int* e2s  = (const int*)d_in[20];
    const int* e2d  = (const int*)d_in[21];
    const int* e3s  = (const int*)d_in[22];
    const int* e3d  = (const int*)d_in[23];
    const int* e12s = (const int*)d_in[24];
    const int* e12d = (const int*)d_in[25];
    const int* e13s = (const int*)d_in[26];
    const int* e13d = (const int*)d_in[27];
    float* out = (float*)d_out;

    float *net1, *mid, *n3b, *sum, *allm;
    cudaGetSymbolAddress((void**)&net1, g_net1);
    cudaGetSymbolAddress((void**)&mid,  g_mid);
    cudaGetSymbolAddress((void**)&n3b,  g_n3b);
    cudaGetSymbolAddress((void**)&sum,  g_sum);
    cudaGetSymbolAddress((void**)&allm, g_allm);
    int *c_e1s, *c_e2s, *c_e3s, *c_e1d, *c_e2d, *c_e3d;
    int *c_e12d, *c_e12s, *c_e13d, *c_e13s;
    cudaGetSymbolAddress((void**)&c_e1s,  g_c_e1s);
    cudaGetSymbolAddress((void**)&c_e2s,  g_c_e2s);
    cudaGetSymbolAddress((void**)&c_e3s,  g_c_e3s);
    cudaGetSymbolAddress((void**)&c_e1d,  g_c_e1d);
    cudaGetSymbolAddress((void**)&c_e2d,  g_c_e2d);
    cudaGetSymbolAddress((void**)&c_e3d,  g_c_e3d);
    cudaGetSymbolAddress((void**)&c_e12d, g_c_e12d);
    cudaGetSymbolAddress((void**)&c_e12s, g_c_e12s);
    cudaGetSymbolAddress((void**)&c_e13d, g_c_e13d);
    cudaGetSymbolAddress((void**)&c_e13s, g_c_e13s);

    cudaFuncSetAttribute(k_gemm_relu, cudaFuncAttributeMaxDynamicSharedMemorySize, GEMM_SMEM);

    const int T = 256;
    const int ZB_MID = (NM * DD / 4 + T - 1) / T;   // zero blocks for NM*128 floats
    const int ZB_SUM = (N0 * DD / 4 + T - 1) / T;
    const int SB_E   = (NE + 7) / 8;                // 8 warps(edges) per block
    const int SB_E12 = (NE12 + 7) / 8;
    const int FB_MID = (NM * DD / 4 + T - 1) / T;
    const int GB     = (N0 + 31) / 32;

    // counts (once; reused read-only through the whole sequence)
    k_zero_counts<<<(N0 + T - 1) / T, T>>>();
    k_count<<<(NE + T - 1) / T, T>>>(e1s, e1d, e2s, e2d, e3s, e3d,
                                     e12s, e12d, e13s, e13d);

    // ---- net1 = (scatter_mean(x_node[e1s]*w1 -> e1d) + x1) * 0.5  (shared) ----
    k_zero_f<<<ZB_MID, T>>>((float4*)net1, NM * DD / 4);
    k_scatter<<<SB_E, T>>>(x_node, e1s, e1d, w1, net1, NE);
    k_finmid<<<FB_MID, T>>>(net1, c_e1d, x1, NM);

    // ---- short path 1 -> allm[:,0,:] ----
    k_zero_f<<<ZB_SUM, T>>>((float4*)sum, N0 * DD / 4);
    k_scatter<<<SB_E, T>>>(net1, e1d, e1s, nullptr, sum, NE);
    k_gemm_relu<<<GB, T, GEMM_SMEM>>>(sum, c_e1s, W1, b1, allm + 0 * DD);

    // ---- short path 2 -> allm[:,1,:] ----
    k_zero_f<<<ZB_MID, T>>>((float4*)mid, NM * DD / 4);
    k_scatter<<<SB_E, T>>>(x_node, e2s, e2d, w2, mid, NE);
    k_finmid<<<FB_MID, T>>>(mid, c_e2d, x2, NM);
    k_zero_f<<<ZB_SUM, T>>>((float4*)sum, N0 * DD / 4);
    k_scatter<<<SB_E, T>>>(mid, e2d, e2s, nullptr, sum, NE);
    k_gemm_relu<<<GB, T, GEMM_SMEM>>>(sum, c_e2s, W2, b2, allm + 1 * DD);

    // ---- short path 3 -> allm[:,2,:] ----
    k_zero_f<<<ZB_MID, T>>>((float4*)mid, NM * DD / 4);
    k_scatter<<<SB_E, T>>>(x_node, e3s, e3d, w3, mid, NE);
    k_finmid<<<FB_MID, T>>>(mid, c_e3d, x3, NM);
    k_zero_f<<<ZB_SUM, T>>>((float4*)sum, N0 * DD / 4);
    k_scatter<<<SB_E, T>>>(mid, e3d, e3s, nullptr, sum, NE);
    k_gemm_relu<<<GB, T, GEMM_SMEM>>>(sum, c_e3s, W3, b3, allm + 2 * DD);

    // ---- long path 1-2-1 -> allm[:,3,:] ----
    k_zero_f<<<ZB_MID, T>>>((float4*)mid, NM * DD / 4);
    k_scatter<<<SB_E12, T>>>(net1, e12s, e12d, nullptr, mid, NE12);
    k_finmid<<<FB_MID, T>>>(mid, c_e12d, x2, NM);          // n2
    k_zero_f<<<ZB_MID, T>>>((float4*)n3b, NM * DD / 4);
    k_scatter<<<SB_E12, T>>>(mid, e12d, e12s, nullptr, n3b, NE12);
    k_finmid<<<FB_MID, T>>>(n3b, c_e12s, x1, NM);          // n3
    k_zero_f<<<ZB_SUM, T>>>((float4*)sum, N0 * DD / 4);
    k_scatter<<<SB_E, T>>>(n3b, e1d, e1s, w1, sum, NE);
    k_gemm_relu<<<GB, T, GEMM_SMEM>>>(sum, c_e1s, W121, b121, allm + 3 * DD);

    // ---- long path 1-3-1 -> allm[:,4,:] ----
    k_zero_f<<<ZB_MID, T>>>((float4*)mid, NM * DD / 4);
    k_scatter<<<SB_E12, T>>>(net1, e13s, e13d, nullptr, mid, NE12);
    k_finmid<<<FB_MID, T>>>(mid, c_e13d, x3, NM);
    k_zero_f<<<ZB_MID, T>>>((float4*)n3b, NM * DD / 4);
    k_scatter<<<SB_E12, T>>>(mid, e13d, e13s, nullptr, n3b, NE12);
    k_finmid<<<FB_MID, T>>>(n3b, c_e13s, x1, NM);
    k_zero_f<<<ZB_SUM, T>>>((float4*)sum, N0 * DD / 4);
    k_scatter<<<SB_E, T>>>(n3b, e1d, e1s, w1, sum, NE);
    k_gemm_relu<<<GB, T, GEMM_SMEM>>>(sum, c_e1s, W131, b131, allm + 4 * DD);

    // ---- attention combine ----
    k_att<<<(N0 + 7) / 8, T>>>(attv, out);
}

// round 2
// speedup vs baseline: 1.4569x; 1.4569x over previous
#include <cuda_runtime.h>

#define N0   50000
#define NM   25000
#define DD   128
#define NE   800000
#define NE12 400000

// ---------------- CSR list layout (10 lists) ----------------
// count/cursor bases
#define B_E1D  0
#define B_E1S  (B_E1D + NM)
#define B_E2D  (B_E1S + N0)
#define B_E2S  (B_E2D + NM)
#define B_E3D  (B_E2S + N0)
#define B_E3S  (B_E3D + NM)
#define B_E12D (B_E3S + N0)
#define B_E12S (B_E12D + NM)
#define B_E13D (B_E12S + NM)
#define B_E13S (B_E13D + NM)
#define TOTC   (B_E13S + NM)
// offsets bases (each list gets n+1)
#define OB_E1D  0
#define OB_E1S  (OB_E1D + NM + 1)
#define OB_E2D  (OB_E1S + N0 + 1)
#define OB_E2S  (OB_E2D + NM + 1)
#define OB_E3D  (OB_E2S + N0 + 1)
#define OB_E3S  (OB_E3D + NM + 1)
#define OB_E12D (OB_E3S + N0 + 1)
#define OB_E12S (OB_E12D + NM + 1)
#define OB_E13D (OB_E12S + NM + 1)
#define OB_E13S (OB_E13D + NM + 1)
#define TOTO    (OB_E13S + NM + 1)
// permuted gather-index bases
#define GI_E1D  0
#define GI_E1S  (GI_E1D + NE)
#define GI_E2D  (GI_E1S + NE)
#define GI_E2S  (GI_E2D + NE)
#define GI_E3D  (GI_E2S + NE)
#define GI_E3S  (GI_E3D + NE)
#define GI_E12D (GI_E3S + NE)
#define GI_E12S (GI_E12D + NE12)
#define GI_E13D (GI_E12S + NE12)
#define GI_E13S (GI_E13D + NE12)
#define TOTGI   (GI_E13S + NE12)
// permuted weight bases (only 4 weighted lists)
#define GW_E1D  0
#define GW_E1S  (GW_E1D + NE)
#define GW_E2D  (GW_E1S + NE)
#define GW_E3D  (GW_E2D + NE)
#define TOTGW   (GW_E3D + NE)

// ---------------- static device scratch ----------------
__device__ int   g_cnt[TOTC];
__device__ int   g_cur[TOTC];
__device__ int   g_offs[TOTO];
__device__ int   g_gi[TOTGI];
__device__ float g_gw[TOTGW];

__device__ float g_net1[NM * DD];
__device__ float g_mid [NM * DD];
__device__ float g_n3b [NM * DD];
__device__ float g_sum [N0 * DD];
__device__ float g_allm[(long long)N0 * 5 * DD];

__constant__ int c_lbase[10] = {B_E1D,B_E1S,B_E2D,B_E2S,B_E3D,B_E3S,B_E12D,B_E12S,B_E13D,B_E13S};
__constant__ int c_obase[10] = {OB_E1D,OB_E1S,OB_E2D,OB_E2S,OB_E3D,OB_E3S,OB_E12D,OB_E12S,OB_E13D,OB_E13S};
__constant__ int c_ln[10]    = {NM,N0,NM,N0,NM,N0,NM,NM,NM,NM};

// ---------------- CSR build ----------------
__global__ void k_zero_cnt() {
    int i = blockIdx.x * blockDim.x + threadIdx.x;
    if (i < TOTC) g_cnt[i] = 0;
}

__global__ void k_count(const int* __restrict__ e1s, const int* __restrict__ e1d,
                        const int* __restrict__ e2s, const int* __restrict__ e2d,
                        const int* __restrict__ e3s, const int* __restrict__ e3d,
                        const int* __restrict__ e12s, const int* __restrict__ e12d,
                        const int* __restrict__ e13s, const int* __restrict__ e13d) {
    int i = blockIdx.x * blockDim.x + threadIdx.x;
    if (i < NE) {
        atomicAdd(&g_cnt[B_E1D + e1d[i]], 1); atomicAdd(&g_cnt[B_E1S + e1s[i]], 1);
        atomicAdd(&g_cnt[B_E2D + e2d[i]], 1); atomicAdd(&g_cnt[B_E2S + e2s[i]], 1);
        atomicAdd(&g_cnt[B_E3D + e3d[i]], 1); atomicAdd(&g_cnt[B_E3S + e3s[i]], 1);
    }
    if (i < NE12) {
        atomicAdd(&g_cnt[B_E12D + e12d[i]], 1); atomicAdd(&g_cnt[B_E12S + e12s[i]], 1);
        atomicAdd(&g_cnt[B_E13D + e13d[i]], 1); atomicAdd(&g_cnt[B_E13S + e13s[i]], 1);
    }
}

// one block per list: exclusive scan of counts -> offs (+ total), seed cursors
__global__ void k_scan() {
    __shared__ int sh[1024];
    int b = blockIdx.x;
    int n  = c_ln[b];
    int cb = c_lbase[b];
    int ob = c_obase[b];
    int t = threadIdx.x;
    int chunk = (n + 1023) >> 10;
    int lo = t * chunk;
    int hi = lo + chunk; if (hi > n) hi = n; if (lo > n) lo = n;
    int s = 0;
    for (int i = lo; i < hi; i++) s += g_cnt[cb + i];
    sh[t] = s;
    __syncthreads();
    for (int d = 1; d < 1024; d <<= 1) {
        int v = (t >= d) ? sh[t - d] : 0;
        __syncthreads();
        sh[t] += v;
        __syncthreads();
    }
    int run = (t == 0) ? 0 : sh[t - 1];
    for (int i = lo; i < hi; i++) {
        g_offs[ob + i] = run;
        g_cur [cb + i] = run;
        run += g_cnt[cb + i];
    }
    if (t == 1023) g_offs[ob + n] = sh[1023];
}

// fill one CSR list: gi[pos] = other endpoint, gw[pos] = weight (optional)
__global__ void k_fill(const int* __restrict__ tgt, const int* __restrict__ oth,
                       const float* __restrict__ w,
                       int* __restrict__ cur, int* __restrict__ gi,
                       float* __restrict__ gw, int ne) {
    int e = blockIdx.x * blockDim.x + threadIdx.x;
    if (e >= ne) return;
    int t = __ldg(tgt + e);
    int pos = atomicAdd(&cur[t], 1);
    gi[pos] = __ldg(oth + e);
    if (gw) gw[pos] = __ldg(w + e);
}

// ---------------- fused gather-mean(-combine) ----------------
// one warp per target row; out[n] = mean(w*feat[gi]) [opt: (..+xm[n])*0.5]
template<bool HASW, bool COMBINE>
__global__ void k_gather(const float* __restrict__ feat,
                         const int* __restrict__ offs,
                         const int* __restrict__ gi,
                         const float* __restrict__ gw,
                         const float* __restrict__ xm,
                         float* __restrict__ out, int nrow) {
    int gt = blockIdx.x * blockDim.x + threadIdx.x;
    int n = gt >> 5;
    int lane = gt & 31;
    if (n >= nrow) return;
    int beg = __ldg(offs + n);
    int end = __ldg(offs + n + 1);
    float4 acc = make_float4(0.f, 0.f, 0.f, 0.f);
    int e = beg;
    for (; e + 4 <= end; e += 4) {
        int g0 = __ldg(gi + e + 0), g1 = __ldg(gi + e + 1);
        int g2 = __ldg(gi + e + 2), g3 = __ldg(gi + e + 3);
        float4 v0 = __ldg((const float4*)feat + ((long long)g0 << 5) + lane);
        float4 v1 = __ldg((const float4*)feat + ((long long)g1 << 5) + lane);
        float4 v2 = __ldg((const float4*)feat + ((long long)g2 << 5) + lane);
        float4 v3 = __ldg((const float4*)feat + ((long long)g3 << 5) + lane);
        float w0 = 1.f, w1 = 1.f, w2 = 1.f, w3 = 1.f;
        if (HASW) {
            w0 = __ldg(gw + e + 0); w1 = __ldg(gw + e + 1);
            w2 = __ldg(gw + e + 2); w3 = __ldg(gw + e + 3);
        }
        acc.x += v0.x * w0 + v1.x * w1 + v2.x * w2 + v3.x * w3;
        acc.y += v0.y * w0 + v1.y * w1 + v2.y * w2 + v3.y * w3;
        acc.z += v0.z * w0 + v1.z * w1 + v2.z * w2 + v3.z * w3;
        acc.w += v0.w * w0 + v1.w * w1 + v2.w * w2 + v3.w * w3;
    }
    for (; e < end; e++) {
        int g = __ldg(gi + e);
        float4 v = __ldg((const float4*)feat + ((long long)g << 5) + lane);
        float w = HASW ? __ldg(gw + e) : 1.f;
        acc.x += v.x * w; acc.y += v.y * w; acc.z += v.z * w; acc.w += v.w * w;
    }
    int deg = end - beg;
    float r = 1.0f / (float)(deg < 1 ? 1 : deg);
    acc.x *= r; acc.y *= r; acc.z *= r; acc.w *= r;
    if (COMBINE) {
        float4 x = __ldg((const float4*)xm + n * 32 + lane);
        acc.x = (acc.x + x.x) * 0.5f;
        acc.y = (acc.y + x.y) * 0.5f;
        acc.z = (acc.z + x.z) * 0.5f;
        acc.w = (acc.w + x.w) * 0.5f;
    }
    ((float4*)out)[n * 32 + lane] = acc;
}

// ---------------- GEMM + bias + relu (fp32x2 packed FMA) ----------------
// out[n, j] = relu(b[j] + sum_k sin[n,k]*W[j,k]); 64 rows/block, 8 rows/warp
#define GROWS 64
#define GEMM_SMEM ((DD * DD + GROWS * DD) * 4)
__global__ void k_gemm_relu(const float* __restrict__ sin,
                            const float* __restrict__ W,
                            const float* __restrict__ b,
                            float* __restrict__ obase) {
    extern __shared__ float sh[];
    float* Wt = sh;               // [k][j] = W[j][k], 128x128
    float* xs = sh + DD * DD;     // [r][k], 64x128
    int tid = threadIdx.x;

    for (int idx = tid; idx < DD * DD; idx += 256) {
        int j = idx >> 7, k = idx & 127;
        Wt[k * DD + j] = W[idx];
    }
    int row0 = blockIdx.x * GROWS;
    for (int idx = tid; idx < GROWS * DD / 4; idx += 256) {
        int r = idx >> 5;
        int row = row0 + r;
        float4 v = make_float4(0.f, 0.f, 0.f, 0.f);
        if (row < N0) v = __ldg((const float4*)sin + (long long)row * 32 + (idx & 31));
        ((float4*)xs)[idx] = v;
    }
    __syncthreads();

    int warp = tid >> 5, lane = tid & 31;
    int r0 = warp * 8;
    unsigned long long acc[8][2];
    #pragma unroll
    for (int r = 0; r < 8; r++) { acc[r][0] = 0ull; acc[r][1] = 0ull; }

    #pragma unroll 4
    for (int k = 0; k < DD; k++) {
        float4 wv = *(const float4*)(Wt + k * DD + lane * 4);
        unsigned long long wp0, wp1;
        asm("mov.b64 %0, {%1, %2};" : "=l"(wp0) : "f"(wv.x), "f"(wv.y));
        asm("mov.b64 %0, {%1, %2};" : "=l"(wp1) : "f"(wv.z), "f"(wv.w));
        #pragma unroll
        for (int r = 0; r < 8; r++) {
            float x = xs[(r0 + r) * DD + k];
            unsigned long long xp;
            asm("mov.b64 %0, {%1, %1};" : "=l"(xp) : "f"(x));
            asm("fma.rn.f32x2 %0, %1, %2, %0;" : "+l"(acc[r][0]) : "l"(xp), "l"(wp0));
            asm("fma.rn.f32x2 %0, %1, %2, %0;" : "+l"(acc[r][1]) : "l"(xp), "l"(wp1));
        }
    }

    float4 bb = __ldg((const float4*)b + lane);
    #pragma unroll
    for (int r = 0; r < 8; r++) {
        int row = row0 + r0 + r;
        if (row >= N0) continue;
        float o0, o1, o2, o3;
        asm("mov.b64 {%0, %1}, %2;" : "=f"(o0), "=f"(o1) : "l"(acc[r][0]));
        asm("mov.b64 {%0, %1}, %2;" : "=f"(o2), "=f"(o3) : "l"(acc[r][1]));
        float4 o;
        o.x = fmaxf(o0 + bb.x, 0.f);
        o.y = fmaxf(o1 + bb.y, 0.f);
        o.z = fmaxf(o2 + bb.z, 0.f);
        o.w = fmaxf(o3 + bb.w, 0.f);
        *(float4*)(obase + (long long)row * (5 * DD) + lane * 4) = o;
    }
}

// ---------------- attention combine ----------------
__global__ void k_att(const float* __restrict__ attv, float* __restrict__ out) {
    int gt = blockIdx.x * blockDim.x + threadIdx.x;
    int n = gt >> 5;
    int lane = gt & 31;
    if (n >= N0) return;
    const float4* base = (const float4*)(g_allm + (long long)n * (5 * DD));
    float4 a[5];
    float sc[5];
    #pragma unroll
    for (int p = 0; p < 5; p++) {
        a[p] = base[p * 32 + lane];
        float4 av = __ldg((const float4*)attv + p * 32 + lane);
        float d = a[p].x * av.x + a[p].y * av.y + a[p].z * av.z + a[p].w * av.w;
        #pragma unroll
        for (int o = 16; o; o >>= 1) d += __shfl_xor_sync(0xFFFFFFFFu, d, o);
        sc[p] = d;
    }
    float m = sc[0];
    #pragma unroll
    for (int p = 1; p < 5; p++) m = fmaxf(m, sc[p]);
    float ssum = 0.f;
    #pragma unroll
    for (int p = 0; p < 5; p++) { sc[p] = __expf(sc[p] - m); ssum += sc[p]; }
    float inv = 1.0f / ssum;
    float4 o = make_float4(0.f, 0.f, 0.f, 0.f);
    #pragma unroll
    for (int p = 0; p < 5; p++) {
        float wgt = sc[p] * inv;
        o.x += wgt * a[p].x; o.y += wgt * a[p].y;
        o.z += wgt * a[p].z; o.w += wgt * a[p].w;
    }
    ((float4*)out)[(long long)n * 32 + lane] = o;
}

// ---------------- host orchestration ----------------
extern "C" void kernel_launch(void* const* d_in, const int* in_sizes, int n_in,
                              void* d_out, int out_size) {
    const float* x_node = (const float*)d_in[0];
    const float* x1   = (const float*)d_in[1];
    const float* x2   = (const float*)d_in[2];
    const float* x3   = (const float*)d_in[3];
    const float* w1   = (const float*)d_in[4];
    const float* w2   = (const float*)d_in[5];
    const float* w3   = (const float*)d_in[6];
    const float* W1   = (const float*)d_in[7];
    const float* b1   = (const float*)d_in[8];
    const float* W2   = (const float*)d_in[9];
    const float* b2   = (const float*)d_in[10];
    const float* W3   = (const float*)d_in[11];
    const float* b3   = (const float*)d_in[12];
    const float* W121 = (const float*)d_in[13];
    const float* b121 = (const float*)d_in[14];
    const float* W131 = (const float*)d_in[15];
    const float* b131 = (const float*)d_in[16];
    const float* attv = (const float*)d_in[17];
    const int* e1s  = (const int*)d_in[18];
    const int* e1d  = (const int*)d_in[19];
    const int* e2s  = (const int*)d_in[20];
    const int* e2d  = (const int*)d_in[21];
    const int* e3s  = (const int*)d_in[22];
    const int* e3d  = (const int*)d_in[23];
    const int* e12s = (const int*)d_in[24];
    const int* e12d = (const int*)d_in[25];
    const int* e13s = (const int*)d_in[26];
    const int* e13d = (const int*)d_in[27];
    float* out = (float*)d_out;

    float *net1, *mid, *n3b, *sum, *allm, *gw;
    int *cur, *offs, *gi;
    cudaGetSymbolAddress((void**)&net1, g_net1);
    cudaGetSymbolAddress((void**)&mid,  g_mid);
    cudaGetSymbolAddress((void**)&n3b,  g_n3b);
    cudaGetSymbolAddress((void**)&sum,  g_sum);
    cudaGetSymbolAddress((void**)&allm, g_allm);
    cudaGetSymbolAddress((void**)&cur,  g_cur);
    cudaGetSymbolAddress((void**)&offs, g_offs);
    cudaGetSymbolAddress((void**)&gi,   g_gi);
    cudaGetSymbolAddress((void**)&gw,   g_gw);

    cudaFuncSetAttribute(k_gemm_relu, cudaFuncAttributeMaxDynamicSharedMemorySize, GEMM_SMEM);

    const int T = 256;
    const int GB   = (N0 + GROWS - 1) / GROWS;
    const int GA_M = (NM * 32 + T - 1) / T;   // gather grid, NM targets
    const int GA_0 = (N0 * 32 + T - 1) / T;   // gather grid, N0 targets

    // ---- CSR build ----
    k_zero_cnt<<<(TOTC + T - 1) / T, T>>>();
    k_count<<<(NE + T - 1) / T, T>>>(e1s, e1d, e2s, e2d, e3s, e3d,
                                     e12s, e12d, e13s, e13d);
    k_scan<<<10, 1024>>>();
    const int FB   = (NE + T - 1) / T;
    const int FB12 = (NE12 + T - 1) / T;
    k_fill<<<FB, T>>>(e1d, e1s, w1, cur + B_E1D, gi + GI_E1D, gw + GW_E1D, NE);
    k_fill<<<FB, T>>>(e1s, e1d, w1, cur + B_E1S, gi + GI_E1S, gw + GW_E1S, NE);
    k_fill<<<FB, T>>>(e2d, e2s, w2, cur + B_E2D, gi + GI_E2D, gw + GW_E2D, NE);
    k_fill<<<FB, T>>>(e2s, e2d, nullptr, cur + B_E2S, gi + GI_E2S, nullptr, NE);
    k_fill<<<FB, T>>>(e3d, e3s, w3, cur + B_E3D, gi + GI_E3D, gw + GW_E3D, NE);
    k_fill<<<FB, T>>>(e3s, e3d, nullptr, cur + B_E3S, gi + GI_E3S, nullptr, NE);
    k_fill<<<FB12, T>>>(e12d, e12s, nullptr, cur + B_E12D, gi + GI_E12D, nullptr, NE12);
    k_fill<<<FB12, T>>>(e12s, e12d, nullptr, cur + B_E12S, gi + GI_E12S, nullptr, NE12);
    k_fill<<<FB12, T>>>(e13d, e13s, nullptr, cur + B_E13D, gi + GI_E13D, nullptr, NE12);
    k_fill<<<FB12, T>>>(e13s, e13d, nullptr, cur + B_E13S, gi + GI_E13S, nullptr, NE12);

    // ---- net1 = (mean(x_node[e1s]*w1 -> e1d) + x1)*0.5 (shared) ----
    k_gather<true, true><<<GA_M, T>>>(x_node, offs + OB_E1D, gi + GI_E1D,
                                      gw + GW_E1D, x1, net1, NM);

    // ---- short path 1 -> allm[:,0,:] ----
    k_gather<false, false><<<GA_0, T>>>(net1, offs + OB_E1S, gi + GI_E1S,
                                        nullptr, nullptr, sum, N0);
    k_gemm_relu<<<GB, T, GEMM_SMEM>>>(sum, W1, b1, allm + 0 * DD);

    // ---- short path 2 -> allm[:,1,:] ----
    k_gather<true, true><<<GA_M, T>>>(x_node, offs + OB_E2D, gi + GI_E2D,
                                      gw + GW_E2D, x2, mid, NM);
    k_gather<false, false><<<GA_0, T>>>(mid, offs + OB_E2S, gi + GI_E2S,
                                        nullptr, nullptr, sum, N0);
    k_gemm_relu<<<GB, T, GEMM_SMEM>>>(sum, W2, b2, allm + 1 * DD);

    // ---- short path 3 -> allm[:,2,:] ----
    k_gather<true, true><<<GA_M, T>>>(x_node, offs + OB_E3D, gi + GI_E3D,
                                      gw + GW_E3D, x3, mid, NM);
    k_gather<false, false><<<GA_0, T>>>(mid, offs + OB_E3S, gi + GI_E3S,
                                        nullptr, nullptr, sum, N0);
    k_gemm_relu<<<GB, T, GEMM_SMEM>>>(sum, W3, b3, allm + 2 * DD);

    // ---- long path 1-2-1 -> allm[:,3,:] ----
    k_gather<false, true><<<GA_M, T>>>(net1, offs + OB_E12D, gi + GI_E12D,
                                       nullptr, x2, mid, NM);          // n2
    k_gather<false, true><<<GA_M, T>>>(mid, offs + OB_E12S, gi + GI_E12S,
                                       nullptr, x1, n3b, NM);          // n3
    k_gather<true, false><<<GA_0, T>>>(n3b, offs + OB_E1S, gi + GI_E1S,
                                       gw + GW_E1S, nullptr, sum, N0);
    k_gemm_relu<<<GB, T, GEMM_SMEM>>>(sum, W121, b121, allm + 3 * DD);

    // ---- long path 1-3-1 -> allm[:,4,:] ----
    k_gather<false, true><<<GA_M, T>>>(net1, offs + OB_E13D, gi + GI_E13D,
                                       nullptr, x3, mid, NM);
    k_gather<false, true><<<GA_M, T>>>(mid, offs + OB_E13S, gi + GI_E13S,
                                       nullptr, x1, n3b, NM);
    k_gather<true, false><<<GA_0, T>>>(n3b, offs + OB_E1S, gi + GI_E1S,
                                       gw + GW_E1S, nullptr, sum, N0);
    k_gemm_relu<<<GB, T, GEMM_SMEM>>>(sum, W131, b131, allm + 4 * DD);

    // ---- attention combine ----
    k_att<<<(N0 + 7) / 8, T>>>(attv, out);
}

// round 3
// speedup vs baseline: 1.6936x; 1.1624x over previous
#include <cuda_runtime.h>

#define N0   50000
#define NM   25000
#define DD   128
#define NE   800000
#define NE12 400000

// ---------------- CSR list layout (10 lists) ----------------
#define B_E1D  0
#define B_E1S  (B_E1D + NM)
#define B_E2D  (B_E1S + N0)
#define B_E2S  (B_E2D + NM)
#define B_E3D  (B_E2S + N0)
#define B_E3S  (B_E3D + NM)
#define B_E12D (B_E3S + N0)
#define B_E12S (B_E12D + NM)
#define B_E13D (B_E12S + NM)
#define B_E13S (B_E13D + NM)
#define TOTC   (B_E13S + NM)

#define OB_E1D  0
#define OB_E1S  (OB_E1D + NM + 1)
#define OB_E2D  (OB_E1S + N0 + 1)
#define OB_E2S  (OB_E2D + NM + 1)
#define OB_E3D  (OB_E2S + N0 + 1)
#define OB_E3S  (OB_E3D + NM + 1)
#define OB_E12D (OB_E3S + N0 + 1)
#define OB_E12S (OB_E12D + NM + 1)
#define OB_E13D (OB_E12S + NM + 1)
#define OB_E13S (OB_E13D + NM + 1)
#define TOTO    (OB_E13S + NM + 1)

#define GI_E1D  0
#define GI_E1S  (GI_E1D + NE)
#define GI_E2D  (GI_E1S + NE)
#define GI_E2S  (GI_E2D + NE)
#define GI_E3D  (GI_E2S + NE)
#define GI_E3S  (GI_E3D + NE)
#define GI_E12D (GI_E3S + NE)
#define GI_E12S (GI_E12D + NE12)
#define GI_E13D (GI_E12S + NE12)
#define GI_E13S (GI_E13D + NE12)
#define TOTGI   (GI_E13S + NE12)

#define GW_E1D  0
#define GW_E1S  (GW_E1D + NE)
#define GW_E2D  (GW_E1S + NE)
#define GW_E3D  (GW_E2D + NE)
#define TOTGW   (GW_E3D + NE)

// ---------------- static device scratch ----------------
__device__ int   g_cnt[TOTC];
__device__ int   g_cur[TOTC];
__device__ int   g_offs[TOTO];
__device__ int   g_gi[TOTGI];
__device__ float g_gw[TOTGW];

__device__ float g_net1[NM * DD];
__device__ float g_midB[NM * DD];
__device__ float g_midC[NM * DD];
__device__ float g_midD[NM * DD];
__device__ float g_n3bD[NM * DD];
__device__ float g_midE[NM * DD];
__device__ float g_n3bE[NM * DD];
__device__ float g_sumA[N0 * DD];
__device__ float g_sumB[N0 * DD];
__device__ float g_sumC[N0 * DD];
__device__ float g_sumD[N0 * DD];
__device__ float g_sumE[N0 * DD];
__device__ float g_allm[(long long)N0 * 5 * DD];

__constant__ int c_lbase[10] = {B_E1D,B_E1S,B_E2D,B_E2S,B_E3D,B_E3S,B_E12D,B_E12S,B_E13D,B_E13S};
__constant__ int c_obase[10] = {OB_E1D,OB_E1S,OB_E2D,OB_E2S,OB_E3D,OB_E3S,OB_E12D,OB_E12S,OB_E13D,OB_E13S};
__constant__ int c_ln[10]    = {NM,N0,NM,N0,NM,N0,NM,NM,NM,NM};

// ---------------- CSR build ----------------
__global__ void k_count(const int* __restrict__ e1s, const int* __restrict__ e1d,
                        const int* __restrict__ e2s, const int* __restrict__ e2d,
                        const int* __restrict__ e3s, const int* __restrict__ e3d,
                        const int* __restrict__ e12s, const int* __restrict__ e12d,
                        const int* __restrict__ e13s, const int* __restrict__ e13d) {
    int i = blockIdx.x * blockDim.x + threadIdx.x;
    if (i < NE) {
        atomicAdd(&g_cnt[B_E1D + e1d[i]], 1); atomicAdd(&g_cnt[B_E1S + e1s[i]], 1);
        atomicAdd(&g_cnt[B_E2D + e2d[i]], 1); atomicAdd(&g_cnt[B_E2S + e2s[i]], 1);
        atomicAdd(&g_cnt[B_E3D + e3d[i]], 1); atomicAdd(&g_cnt[B_E3S + e3s[i]], 1);
    }
    if (i < NE12) {
        atomicAdd(&g_cnt[B_E12D + e12d[i]], 1); atomicAdd(&g_cnt[B_E12S + e12s[i]], 1);
        atomicAdd(&g_cnt[B_E13D + e13d[i]], 1); atomicAdd(&g_cnt[B_E13S + e13s[i]], 1);
    }
}

// one block per list: exclusive scan of counts -> offs (+ total), seed cursors
__global__ void k_scan() {
    __shared__ int sh[1024];
    int b = blockIdx.x;
    int n  = c_ln[b];
    int cb = c_lbase[b];
    int ob = c_obase[b];
    int t = threadIdx.x;
    int chunk = (n + 1023) >> 10;
    int lo = t * chunk;
    int hi = lo + chunk; if (hi > n) hi = n; if (lo > n) lo = n;
    int s = 0;
    for (int i = lo; i < hi; i++) s += g_cnt[cb + i];
    sh[t] = s;
    __syncthreads();
    for (int d = 1; d < 1024; d <<= 1) {
        int v = (t >= d) ? sh[t - d] : 0;
        __syncthreads();
        sh[t] += v;
        __syncthreads();
    }
    int run = (t == 0) ? 0 : sh[t - 1];
    for (int i = lo; i < hi; i++) {
        g_offs[ob + i] = run;
        g_cur [cb + i] = run;
        run += g_cnt[cb + i];
    }
    if (t == 1023) g_offs[ob + n] = sh[1023];
}

// fused fill: one thread per edge id handles ALL lists -> 10 independent
// atomic chains in flight per thread (hides ATOMG latency)
__global__ void k_fill_all(const int* __restrict__ e1s, const int* __restrict__ e1d,
                           const int* __restrict__ e2s, const int* __restrict__ e2d,
                           const int* __restrict__ e3s, const int* __restrict__ e3d,
                           const int* __restrict__ e12s, const int* __restrict__ e12d,
                           const int* __restrict__ e13s, const int* __restrict__ e13d,
                           const float* __restrict__ w1, const float* __restrict__ w2,
                           const float* __restrict__ w3) {
    int e = blockIdx.x * blockDim.x + threadIdx.x;
    if (e < NE) {
        int a1 = __ldg(e1s + e), b1 = __ldg(e1d + e); float ww1 = __ldg(w1 + e);
        int a2 = __ldg(e2s + e), b2 = __ldg(e2d + e); float ww2 = __ldg(w2 + e);
        int a3 = __ldg(e3s + e), b3 = __ldg(e3d + e); float ww3 = __ldg(w3 + e);
        int p0 = atomicAdd(&g_cur[B_E1D + b1], 1);
        int p1 = atomicAdd(&g_cur[B_E1S + a1], 1);
        int p2 = atomicAdd(&g_cur[B_E2D + b2], 1);
        int p3 = atomicAdd(&g_cur[B_E2S + a2], 1);
        int p4 = atomicAdd(&g_cur[B_E3D + b3], 1);
        int p5 = atomicAdd(&g_cur[B_E3S + a3], 1);
        g_gi[GI_E1D + p0] = a1; g_gw[GW_E1D + p0] = ww1;
        g_gi[GI_E1S + p1] = b1; g_gw[GW_E1S + p1] = ww1;
        g_gi[GI_E2D + p2] = a2; g_gw[GW_E2D + p2] = ww2;
        g_gi[GI_E2S + p3] = b2;
        g_gi[GI_E3D + p4] = a3; g_gw[GW_E3D + p4] = ww3;
        g_gi[GI_E3S + p5] = b3;
    }
    if (e < NE12) {
        int a4 = __ldg(e12s + e), b4 = __ldg(e12d + e);
        int a5 = __ldg(e13s + e), b5 = __ldg(e13d + e);
        int p6 = atomicAdd(&g_cur[B_E12D + b4], 1);
        int p7 = atomicAdd(&g_cur[B_E12S + a4], 1);
        int p8 = atomicAdd(&g_cur[B_E13D + b5], 1);
        int p9 = atomicAdd(&g_cur[B_E13S + a5], 1);
        g_gi[GI_E12D + p6] = a4;
        g_gi[GI_E12S + p7] = b4;
        g_gi[GI_E13D + p8] = a5;
        g_gi[GI_E13S + p9] = b5;
    }
}

// ---------------- fused gather-mean(-combine) ----------------
template<bool HASW, bool COMBINE>
__global__ void k_gather(const float* __restrict__ feat,
                         const int* __restrict__ offs,
                         const int* __restrict__ gi,
                         const float* __restrict__ gw,
                         const float* __restrict__ xm,
                         float* __restrict__ out, int nrow) {
    int gt = blockIdx.x * blockDim.x + threadIdx.x;
    int n = gt >> 5;
    int lane = gt & 31;
    if (n >= nrow) return;
    int beg = __ldg(offs + n);
    int end = __ldg(offs + n + 1);
    float4 acc = make_float4(0.f, 0.f, 0.f, 0.f);
    int e = beg;
    for (; e + 4 <= end; e += 4) {
        int g0 = __ldg(gi + e + 0), g1 = __ldg(gi + e + 1);
        int g2 = __ldg(gi + e + 2), g3 = __ldg(gi + e + 3);
        float4 v0 = __ldg((const float4*)feat + ((long long)g0 << 5) + lane);
        float4 v1 = __ldg((const float4*)feat + ((long long)g1 << 5) + lane);
        float4 v2 = __ldg((const float4*)feat + ((long long)g2 << 5) + lane);
        float4 v3 = __ldg((const float4*)feat + ((long long)g3 << 5) + lane);
        float w0 = 1.f, w1 = 1.f, w2 = 1.f, w3 = 1.f;
        if (HASW) {
            w0 = __ldg(gw + e + 0); w1 = __ldg(gw + e + 1);
            w2 = __ldg(gw + e + 2); w3 = __ldg(gw + e + 3);
        }
        acc.x += v0.x * w0 + v1.x * w1 + v2.x * w2 + v3.x * w3;
        acc.y += v0.y * w0 + v1.y * w1 + v2.y * w2 + v3.y * w3;
        acc.z += v0.z * w0 + v1.z * w1 + v2.z * w2 + v3.z * w3;
        acc.w += v0.w * w0 + v1.w * w1 + v2.w * w2 + v3.w * w3;
    }
    for (; e < end; e++) {
        int g = __ldg(gi + e);
        float4 v = __ldg((const float4*)feat + ((long long)g << 5) + lane);
        float w = HASW ? __ldg(gw + e) : 1.f;
        acc.x += v.x * w; acc.y += v.y * w; acc.z += v.z * w; acc.w += v.w * w;
    }
    int deg = end - beg;
    float r = 1.0f / (float)(deg < 1 ? 1 : deg);
    acc.x *= r; acc.y *= r; acc.z *= r; acc.w *= r;
    if (COMBINE) {
        float4 x = __ldg((const float4*)xm + n * 32 + lane);
        acc.x = (acc.x + x.x) * 0.5f;
        acc.y = (acc.y + x.y) * 0.5f;
        acc.z = (acc.z + x.z) * 0.5f;
        acc.w = (acc.w + x.w) * 0.5f;
    }
    ((float4*)out)[n * 32 + lane] = acc;
}

// ---------------- GEMM + bias + relu (fp32x2 packed FMA) ----------------
#define GROWS 64
#define GEMM_SMEM ((DD * DD + GROWS * DD) * 4)
__global__ void k_gemm_relu(const float* __restrict__ sin,
                            const float* __restrict__ W,
                            const float* __restrict__ b,
                            float* __restrict__ obase) {
    extern __shared__ float sh[];
    float* Wt = sh;               // [k][j] = W[j][k]
    float* xs = sh + DD * DD;     // [r][k]
    int tid = threadIdx.x;

    for (int idx = tid; idx < DD * DD; idx += 256) {
        int j = idx >> 7, k = idx & 127;
        Wt[k * DD + j] = W[idx];
    }
    int row0 = blockIdx.x * GROWS;
    for (int idx = tid; idx < GROWS * DD / 4; idx += 256) {
        int r = idx >> 5;
        int row = row0 + r;
        float4 v = make_float4(0.f, 0.f, 0.f, 0.f);
        if (row < N0) v = __ldg((const float4*)sin + (long long)row * 32 + (idx & 31));
        ((float4*)xs)[idx] = v;
    }
    __syncthreads();

    int warp = tid >> 5, lane = tid & 31;
    int r0 = warp * 8;
    unsigned long long acc[8][2];
    #pragma unroll
    for (int r = 0; r < 8; r++) { acc[r][0] = 0ull; acc[r][1] = 0ull; }

    #pragma unroll 4
    for (int k = 0; k < DD; k++) {
        float4 wv = *(const float4*)(Wt + k * DD + lane * 4);
        unsigned long long wp0, wp1;
        asm("mov.b64 %0, {%1, %2};" : "=l"(wp0) : "f"(wv.x), "f"(wv.y));
        asm("mov.b64 %0, {%1, %2};" : "=l"(wp1) : "f"(wv.z), "f"(wv.w));
        #pragma unroll
        for (int r = 0; r < 8; r++) {
            float x = xs[(r0 + r) * DD + k];
            unsigned long long xp;
            asm("mov.b64 %0, {%1, %1};" : "=l"(xp) : "f"(x));
            asm("fma.rn.f32x2 %0, %1, %2, %0;" : "+l"(acc[r][0]) : "l"(xp), "l"(wp0));
            asm("fma.rn.f32x2 %0, %1, %2, %0;" : "+l"(acc[r][1]) : "l"(xp), "l"(wp1));
        }
    }

    float4 bb = __ldg((const float4*)b + lane);
    #pragma unroll
    for (int r = 0; r < 8; r++) {
        int row = row0 + r0 + r;
        if (row >= N0) continue;
        float o0, o1, o2, o3;
        asm("mov.b64 {%0, %1}, %2;" : "=f"(o0), "=f"(o1) : "l"(acc[r][0]));
        asm("mov.b64 {%0, %1}, %2;" : "=f"(o2), "=f"(o3) : "l"(acc[r][1]));
        float4 o;
        o.x = fmaxf(o0 + bb.x, 0.f);
        o.y = fmaxf(o1 + bb.y, 0.f);
        o.z = fmaxf(o2 + bb.z, 0.f);
        o.w = fmaxf(o3 + bb.w, 0.f);
        *(float4*)(obase + (long long)row * (5 * DD) + lane * 4) = o;
    }
}

// ---------------- attention combine ----------------
__global__ void k_att(const float* __restrict__ attv, float* __restrict__ out) {
    int gt = blockIdx.x * blockDim.x + threadIdx.x;
    int n = gt >> 5;
    int lane = gt & 31;
    if (n >= N0) return;
    const float4* base = (const float4*)(g_allm + (long long)n * (5 * DD));
    float4 a[5];
    float sc[5];
    #pragma unroll
    for (int p = 0; p < 5; p++) {
        a[p] = base[p * 32 + lane];
        float4 av = __ldg((const float4*)attv + p * 32 + lane);
        float d = a[p].x * av.x + a[p].y * av.y + a[p].z * av.z + a[p].w * av.w;
        #pragma unroll
        for (int o = 16; o; o >>= 1) d += __shfl_xor_sync(0xFFFFFFFFu, d, o);
        sc[p] = d;
    }
    float m = sc[0];
    #pragma unroll
    for (int p = 1; p < 5; p++) m = fmaxf(m, sc[p]);
    float ssum = 0.f;
    #pragma unroll
    for (int p = 0; p < 5; p++) { sc[p] = __expf(sc[p] - m); ssum += sc[p]; }
    float inv = 1.0f / ssum;
    float4 o = make_float4(0.f, 0.f, 0.f, 0.f);
    #pragma unroll
    for (int p = 0; p < 5; p++) {
        float wgt = sc[p] * inv;
        o.x += wgt * a[p].x; o.y += wgt * a[p].y;
        o.z += wgt * a[p].z; o.w += wgt * a[p].w;
    }
    ((float4*)out)[(long long)n * 32 + lane] = o;
}

// ---------------- host orchestration ----------------
extern "C" void kernel_launch(void* const* d_in, const int* in_sizes, int n_in,
                              void* d_out, int out_size) {
    const float* x_node = (const float*)d_in[0];
    const float* x1   = (const float*)d_in[1];
    const float* x2   = (const float*)d_in[2];
    const float* x3   = (const float*)d_in[3];
    const float* w1   = (const float*)d_in[4];
    const float* w2   = (const float*)d_in[5];
    const float* w3   = (const float*)d_in[6];
    const float* W1   = (const float*)d_in[7];
    const float* b1   = (const float*)d_in[8];
    const float* W2   = (const float*)d_in[9];
    const float* b2   = (const float*)d_in[10];
    const float* W3   = (const float*)d_in[11];
    const float* b3   = (const float*)d_in[12];
    const float* W121 = (const float*)d_in[13];
    const float* b121 = (const float*)d_in[14];
    const float* W131 = (const float*)d_in[15];
    const float* b131 = (const float*)d_in[16];
    const float* attv = (const float*)d_in[17];
    const int* e1s  = (const int*)d_in[18];
    const int* e1d  = (const int*)d_in[19];
    const int* e2s  = (const int*)d_in[20];
    const int* e2d  = (const int*)d_in[21];
    const int* e3s  = (const int*)d_in[22];
    const int* e3d  = (const int*)d_in[23];
    const int* e12s = (const int*)d_in[24];
    const int* e12d = (const int*)d_in[25];
    const int* e13s = (const int*)d_in[26];
    const int* e13d = (const int*)d_in[27];
    float* out = (float*)d_out;

    float *net1, *midB, *midC, *midD, *n3bD, *midE, *n3bE;
    float *sumA, *sumB, *sumC, *sumD, *sumE, *allm, *gw;
    int *cnt, *cur, *offs, *gi;
    cudaGetSymbolAddress((void**)&net1, g_net1);
    cudaGetSymbolAddress((void**)&midB, g_midB);
    cudaGetSymbolAddress((void**)&midC, g_midC);
    cudaGetSymbolAddress((void**)&midD, g_midD);
    cudaGetSymbolAddress((void**)&n3bD, g_n3bD);
    cudaGetSymbolAddress((void**)&midE, g_midE);
    cudaGetSymbolAddress((void**)&n3bE, g_n3bE);
    cudaGetSymbolAddress((void**)&sumA, g_sumA);
    cudaGetSymbolAddress((void**)&sumB, g_sumB);
    cudaGetSymbolAddress((void**)&sumC, g_sumC);
    cudaGetSymbolAddress((void**)&sumD, g_sumD);
    cudaGetSymbolAddress((void**)&sumE, g_sumE);
    cudaGetSymbolAddress((void**)&allm, g_allm);
    cudaGetSymbolAddress((void**)&cnt,  g_cnt);
    cudaGetSymbolAddress((void**)&cur,  g_cur);
    cudaGetSymbolAddress((void**)&offs, g_offs);
    cudaGetSymbolAddress((void**)&gi,   g_gi);
    cudaGetSymbolAddress((void**)&gw,   g_gw);

    cudaFuncSetAttribute(k_gemm_relu, cudaFuncAttributeMaxDynamicSharedMemorySize, GEMM_SMEM);

    // lazy-once host resources (no device memory involved)
    static cudaStream_t s1 = nullptr, s2 = nullptr;
    static cudaEvent_t evBuild, evNet1, evS1, evS2;
    if (!s1) {
        cudaStreamCreateWithFlags(&s1, cudaStreamNonBlocking);
        cudaStreamCreateWithFlags(&s2, cudaStreamNonBlocking);
        cudaEventCreateWithFlags(&evBuild, cudaEventDisableTiming);
        cudaEventCreateWithFlags(&evNet1,  cudaEventDisableTiming);
        cudaEventCreateWithFlags(&evS1,    cudaEventDisableTiming);
        cudaEventCreateWithFlags(&evS2,    cudaEventDisableTiming);
    }

    const int T = 256;
    const int GB   = (N0 + GROWS - 1) / GROWS;
    const int GA_M = (NM * 32 + T - 1) / T;
    const int GA_0 = (N0 * 32 + T - 1) / T;
    const int EB   = (NE + T - 1) / T;

    // ================= CSR build (stream 0) =================
    cudaMemsetAsync(cnt, 0, TOTC * sizeof(int), 0);
    k_count<<<EB, T>>>(e1s, e1d, e2s, e2d, e3s, e3d, e12s, e12d, e13s, e13d);
    k_scan<<<10, 1024>>>();
    k_fill_all<<<EB, T>>>(e1s, e1d, e2s, e2d, e3s, e3d, e12s, e12d, e13s, e13d,
                          w1, w2, w3);
    cudaEventRecord(evBuild, 0);

    // fork
    cudaStreamWaitEvent(s1, evBuild, 0);
    cudaStreamWaitEvent(s2, evBuild, 0);

    // ========== stream 0: net1 -> long path 1-2-1 ==========
    k_gather<true, true><<<GA_M, T>>>(x_node, offs + OB_E1D, gi + GI_E1D,
                                      gw + GW_E1D, x1, net1, NM);
    cudaEventRecord(evNet1, 0);
    k_gather<false, true><<<GA_M, T>>>(net1, offs + OB_E12D, gi + GI_E12D,
                                       nullptr, x2, midD, NM);
    k_gather<false, true><<<GA_M, T>>>(midD, offs + OB_E12S, gi + GI_E12S,
                                       nullptr, x1, n3bD, NM);
    k_gather<true, false><<<GA_0, T>>>(n3bD, offs + OB_E1S, gi + GI_E1S,
                                       gw + GW_E1S, nullptr, sumD, N0);
    k_gemm_relu<<<GB, T, GEMM_SMEM>>>(sumD, W121, b121, allm + 3 * DD);

    // ========== stream 1: short path 2, then long path 1-3-1 ==========
    k_gather<true, true><<<GA_M, T, 0, s1>>>(x_node, offs + OB_E2D, gi + GI_E2D,
                                             gw + GW_E2D, x2, midB, NM);
    k_gather<false, false><<<GA_0, T, 0, s1>>>(midB, offs + OB_E2S, gi + GI_E2S,
                                               nullptr, nullptr, sumB, N0);
    k_gemm_relu<<<GB, T, GEMM_SMEM, s1>>>(sumB, W2, b2, allm + 1 * DD);
    cudaStreamWaitEvent(s1, evNet1, 0);
    k_gather<false, true><<<GA_M, T, 0, s1>>>(net1, offs + OB_E13D, gi + GI_E13D,
                                              nullptr, x3, midE, NM);
    k_gather<false, true><<<GA_M, T, 0, s1>>>(midE, offs + OB_E13S, gi + GI_E13S,
                                              nullptr, x1, n3bE, NM);
    k_gather<true, false><<<GA_0, T, 0, s1>>>(n3bE, offs + OB_E1S, gi + GI_E1S,
                                              gw + GW_E1S, nullptr, sumE, N0);
    k_gemm_relu<<<GB, T, GEMM_SMEM, s1>>>(sumE, W131, b131, allm + 4 * DD);
    cudaEventRecord(evS1, s1);

    // ========== stream 2: short path 3, then short path 1 ==========
    k_gather<true, true><<<GA_M, T, 0, s2>>>(x_node, offs + OB_E3D, gi + GI_E3D,
                                             gw + GW_E3D, x3, midC, NM);
    k_gather<false, false><<<GA_0, T, 0, s2>>>(midC, offs + OB_E3S, gi + GI_E3S,
                                               nullptr, nullptr, sumC, N0);
    k_gemm_relu<<<GB, T, GEMM_SMEM, s2>>>(sumC, W3, b3, allm + 2 * DD);
    cudaStreamWaitEvent(s2, evNet1, 0);
    k_gather<false, false><<<GA_0, T, 0, s2>>>(net1, offs + OB_E1S, gi + GI_E1S,
                                               nullptr, nullptr, sumA, N0);
    k_gemm_relu<<<GB, T, GEMM_SMEM, s2>>>(sumA, W1, b1, allm + 0 * DD);
    cudaEventRecord(evS2, s2);

    // join + attention combine
    cudaStreamWaitEvent(0, evS1, 0);
    cudaStreamWaitEvent(0, evS2, 0);
    k_att<<<(N0 + 7) / 8, T>>>(attv, out);
}

// round 4
// speedup vs baseline: 1.7441x; 1.0298x over previous
#include <cuda_runtime.h>

#define N0   50000
#define NM   25000
#define DD   128
#define NE   800000
#define NE12 400000

// ---------------- CSR list layout (10 lists) ----------------
#define B_E1D  0
#define B_E1S  (B_E1D + NM)
#define B_E2D  (B_E1S + N0)
#define B_E2S  (B_E2D + NM)
#define B_E3D  (B_E2S + N0)
#define B_E3S  (B_E3D + NM)
#define B_E12D (B_E3S + N0)
#define B_E12S (B_E12D + NM)
#define B_E13D (B_E12S + NM)
#define B_E13S (B_E13D + NM)
#define TOTC   (B_E13S + NM)

#define OB_E1D  0
#define OB_E1S  (OB_E1D + NM + 1)
#define OB_E2D  (OB_E1S + N0 + 1)
#define OB_E2S  (OB_E2D + NM + 1)
#define OB_E3D  (OB_E2S + N0 + 1)
#define OB_E3S  (OB_E3D + NM + 1)
#define OB_E12D (OB_E3S + N0 + 1)
#define OB_E12S (OB_E12D + NM + 1)
#define OB_E13D (OB_E12S + NM + 1)
#define OB_E13S (OB_E13D + NM + 1)
#define TOTO    (OB_E13S + NM + 1)

#define GI_E1D  0
#define GI_E1S  (GI_E1D + NE)
#define GI_E2D  (GI_E1S + NE)
#define GI_E2S  (GI_E2D + NE)
#define GI_E3D  (GI_E2S + NE)
#define GI_E3S  (GI_E3D + NE)
#define GI_E12D (GI_E3S + NE)
#define GI_E12S (GI_E12D + NE12)
#define GI_E13D (GI_E12S + NE12)
#define GI_E13S (GI_E13D + NE12)
#define TOTGI   (GI_E13S + NE12)

#define GW_E1D  0
#define GW_E1S  (GW_E1D + NE)
#define GW_E2D  (GW_E1S + NE)
#define GW_E3D  (GW_E2D + NE)
#define TOTGW   (GW_E3D + NE)

// ---------------- static device scratch ----------------
__device__ int   g_cnt[TOTC];
__device__ int   g_cur[TOTC];
__device__ int   g_offs[TOTO];
__device__ int   g_gi[TOTGI];
__device__ float g_gw[TOTGW];

__device__ float g_net1[NM * DD];
__device__ float g_midB[NM * DD];
__device__ float g_midC[NM * DD];
__device__ float g_midD[NM * DD];
__device__ float g_n3bD[NM * DD];
__device__ float g_midE[NM * DD];
__device__ float g_n3bE[NM * DD];
__device__ float g_sumA[N0 * DD];
__device__ float g_sumB[N0 * DD];
__device__ float g_sumC[N0 * DD];
__device__ float g_sumD[N0 * DD];
__device__ float g_sumE[N0 * DD];
__device__ float g_allm[(long long)N0 * 5 * DD];

__constant__ int c_lbase[10] = {B_E1D,B_E1S,B_E2D,B_E2S,B_E3D,B_E3S,B_E12D,B_E12S,B_E13D,B_E13S};
__constant__ int c_obase[10] = {OB_E1D,OB_E1S,OB_E2D,OB_E2S,OB_E3D,OB_E3S,OB_E12D,OB_E12S,OB_E13D,OB_E13S};
__constant__ int c_ln[10]    = {NM,N0,NM,N0,NM,N0,NM,NM,NM,NM};

// ---------------- CSR build ----------------
__global__ void k_count(const int* __restrict__ e1s, const int* __restrict__ e1d,
                        const int* __restrict__ e2s, const int* __restrict__ e2d,
                        const int* __restrict__ e3s, const int* __restrict__ e3d,
                        const int* __restrict__ e12s, const int* __restrict__ e12d,
                        const int* __restrict__ e13s, const int* __restrict__ e13d) {
    int i = blockIdx.x * blockDim.x + threadIdx.x;
    if (i < NE) {
        atomicAdd(&g_cnt[B_E1D + e1d[i]], 1); atomicAdd(&g_cnt[B_E1S + e1s[i]], 1);
        atomicAdd(&g_cnt[B_E2D + e2d[i]], 1); atomicAdd(&g_cnt[B_E2S + e2s[i]], 1);
        atomicAdd(&g_cnt[B_E3D + e3d[i]], 1); atomicAdd(&g_cnt[B_E3S + e3s[i]], 1);
    }
    if (i < NE12) {
        atomicAdd(&g_cnt[B_E12D + e12d[i]], 1); atomicAdd(&g_cnt[B_E12S + e12s[i]], 1);
        atomicAdd(&g_cnt[B_E13D + e13d[i]], 1); atomicAdd(&g_cnt[B_E13S + e13s[i]], 1);
    }
}

__global__ void k_scan() {
    __shared__ int sh[1024];
    int b = blockIdx.x;
    int n  = c_ln[b];
    int cb = c_lbase[b];
    int ob = c_obase[b];
    int t = threadIdx.x;
    int chunk = (n + 1023) >> 10;
    int lo = t * chunk;
    int hi = lo + chunk; if (hi > n) hi = n; if (lo > n) lo = n;
    int s = 0;
    for (int i = lo; i < hi; i++) s += g_cnt[cb + i];
    sh[t] = s;
    __syncthreads();
    for (int d = 1; d < 1024; d <<= 1) {
        int v = (t >= d) ? sh[t - d] : 0;
        __syncthreads();
        sh[t] += v;
        __syncthreads();
    }
    int run = (t == 0) ? 0 : sh[t - 1];
    for (int i = lo; i < hi; i++) {
        g_offs[ob + i] = run;
        g_cur [cb + i] = run;
        run += g_cnt[cb + i];
    }
    if (t == 1023) g_offs[ob + n] = sh[1023];
}

__global__ void k_fill_all(const int* __restrict__ e1s, const int* __restrict__ e1d,
                           const int* __restrict__ e2s, const int* __restrict__ e2d,
                           const int* __restrict__ e3s, const int* __restrict__ e3d,
                           const int* __restrict__ e12s, const int* __restrict__ e12d,
                           const int* __restrict__ e13s, const int* __restrict__ e13d,
                           const float* __restrict__ w1, const float* __restrict__ w2,
                           const float* __restrict__ w3) {
    int e = blockIdx.x * blockDim.x + threadIdx.x;
    if (e < NE) {
        int a1 = __ldg(e1s + e), b1 = __ldg(e1d + e); float ww1 = __ldg(w1 + e);
        int a2 = __ldg(e2s + e), b2 = __ldg(e2d + e); float ww2 = __ldg(w2 + e);
        int a3 = __ldg(e3s + e), b3 = __ldg(e3d + e); float ww3 = __ldg(w3 + e);
        int p0 = atomicAdd(&g_cur[B_E1D + b1], 1);
        int p1 = atomicAdd(&g_cur[B_E1S + a1], 1);
        int p2 = atomicAdd(&g_cur[B_E2D + b2], 1);
        int p3 = atomicAdd(&g_cur[B_E2S + a2], 1);
        int p4 = atomicAdd(&g_cur[B_E3D + b3], 1);
        int p5 = atomicAdd(&g_cur[B_E3S + a3], 1);
        g_gi[GI_E1D + p0] = a1; g_gw[GW_E1D + p0] = ww1;
        g_gi[GI_E1S + p1] = b1; g_gw[GW_E1S + p1] = ww1;
        g_gi[GI_E2D + p2] = a2; g_gw[GW_E2D + p2] = ww2;
        g_gi[GI_E2S + p3] = b2;
        g_gi[GI_E3D + p4] = a3; g_gw[GW_E3D + p4] = ww3;
        g_gi[GI_E3S + p5] = b3;
    }
    if (e < NE12) {
        int a4 = __ldg(e12s + e), b4 = __ldg(e12d + e);
        int a5 = __ldg(e13s + e), b5 = __ldg(e13d + e);
        int p6 = atomicAdd(&g_cur[B_E12D + b4], 1);
        int p7 = atomicAdd(&g_cur[B_E12S + a4], 1);
        int p8 = atomicAdd(&g_cur[B_E13D + b5], 1);
        int p9 = atomicAdd(&g_cur[B_E13S + a5], 1);
        g_gi[GI_E12D + p6] = a4;
        g_gi[GI_E12S + p7] = b4;
        g_gi[GI_E13D + p8] = a5;
        g_gi[GI_E13S + p9] = b5;
    }
}

// ---------------- mega gather: up to 4 CSR lists per launch ----------------
struct GList {
    const float* feat;
    const int*   offs;
    const int*   gi;
    const float* gw;    // null -> unweighted
    const float* xm;    // null -> no combine
    float*       out;
    int          nrow;
    int          blk0;  // first block of this list
};
struct GArgs { GList l[4]; int nlists; };

// 256 threads = 8 warps = 8 target rows per block
__global__ void k_gather_mega(GArgs ga) {
    int li = 0;
    #pragma unroll
    for (int i = 1; i < 4; i++)
        if (i < ga.nlists && (int)blockIdx.x >= ga.l[i].blk0) li = i;
    const GList& L = ga.l[li];

    int n = (blockIdx.x - L.blk0) * 8 + (threadIdx.x >> 5);
    int lane = threadIdx.x & 31;
    if (n >= L.nrow) return;

    const float* feat = L.feat;
    const int*   gi   = L.gi;
    const float* gw   = L.gw;
    int beg = __ldg(L.offs + n);
    int end = __ldg(L.offs + n + 1);
    bool hasw = (gw != nullptr);

    float4 acc = make_float4(0.f, 0.f, 0.f, 0.f);
    int e = beg;
    for (; e + 8 <= end; e += 8) {
        int g[8]; float4 v[8]; float w[8];
        #pragma unroll
        for (int i = 0; i < 8; i++) g[i] = __ldg(gi + e + i);
        #pragma unroll
        for (int i = 0; i < 8; i++)
            v[i] = __ldg((const float4*)feat + ((unsigned)g[i] << 5) + lane);
        #pragma unroll
        for (int i = 0; i < 8; i++) w[i] = hasw ? __ldg(gw + e + i) : 1.f;
        #pragma unroll
        for (int i = 0; i < 8; i++) {
            acc.x += v[i].x * w[i];
            acc.y += v[i].y * w[i];
            acc.z += v[i].z * w[i];
            acc.w += v[i].w * w[i];
        }
    }
    for (; e < end; e++) {
        int g = __ldg(gi + e);
        float4 v = __ldg((const float4*)feat + ((unsigned)g << 5) + lane);
        float w = hasw ? __ldg(gw + e) : 1.f;
        acc.x += v.x * w; acc.y += v.y * w; acc.z += v.z * w; acc.w += v.w * w;
    }
    int deg = end - beg;
    float r = 1.0f / (float)(deg < 1 ? 1 : deg);
    acc.x *= r; acc.y *= r; acc.z *= r; acc.w *= r;
    if (L.xm) {
        float4 x = __ldg((const float4*)L.xm + n * 32 + lane);
        acc.x = (acc.x + x.x) * 0.5f;
        acc.y = (acc.y + x.y) * 0.5f;
        acc.z = (acc.z + x.z) * 0.5f;
        acc.w = (acc.w + x.w) * 0.5f;
    }
    ((float4*)L.out)[n * 32 + lane] = acc;
}

// ---------------- mega GEMM + bias + relu ----------------
#define GROWS 64
#define GBLK  ((N0 + GROWS - 1) / GROWS)
#define WPAD  132
#define GEMM_SMEM ((DD * WPAD + GROWS * DD) * 4)
struct GemmSeg { const float* sin; const float* W; const float* b; float* obase; };
struct GemmArgs { GemmSeg s[3]; };

__global__ void k_gemm_mega(GemmArgs gargs) {
    extern __shared__ float sh[];
    float* Wt = sh;                 // [k][j], pitch WPAD
    float* xs = sh + DD * WPAD;     // [r][k]
    int tid = threadIdx.x;
    int seg = blockIdx.x / GBLK;
    int blk = blockIdx.x % GBLK;
    const GemmSeg& S = gargs.s[seg];

    for (int idx = tid; idx < DD * DD; idx += 256) {
        int j = idx >> 7, k = idx & 127;
        Wt[k * WPAD + j] = S.W[idx];
    }
    int row0 = blk * GROWS;
    for (int idx = tid; idx < GROWS * DD / 4; idx += 256) {
        int r = idx >> 5;
        int row = row0 + r;
        float4 v = make_float4(0.f, 0.f, 0.f, 0.f);
        if (row < N0) v = __ldg((const float4*)S.sin + (long long)row * 32 + (idx & 31));
        ((float4*)xs)[idx] = v;
    }
    __syncthreads();

    int warp = tid >> 5, lane = tid & 31;
    int r0 = warp * 8;
    unsigned long long acc[8][2];
    #pragma unroll
    for (int r = 0; r < 8; r++) { acc[r][0] = 0ull; acc[r][1] = 0ull; }

    #pragma unroll 2
    for (int k0 = 0; k0 < DD; k0 += 4) {
        float4 xv[8];
        #pragma unroll
        for (int r = 0; r < 8; r++)
            xv[r] = *(const float4*)(xs + (r0 + r) * DD + k0);
        #pragma unroll
        for (int kk = 0; kk < 4; kk++) {
            float4 wv = *(const float4*)(Wt + (k0 + kk) * WPAD + lane * 4);
            unsigned long long wp0, wp1;
            asm("mov.b64 %0, {%1, %2};" : "=l"(wp0) : "f"(wv.x), "f"(wv.y));
            asm("mov.b64 %0, {%1, %2};" : "=l"(wp1) : "f"(wv.z), "f"(wv.w));
            #pragma unroll
            for (int r = 0; r < 8; r++) {
                float x = (kk == 0) ? xv[r].x : (kk == 1) ? xv[r].y
                        : (kk == 2) ? xv[r].z : xv[r].w;
                unsigned long long xp;
                asm("mov.b64 %0, {%1, %1};" : "=l"(xp) : "f"(x));
                asm("fma.rn.f32x2 %0, %1, %2, %0;" : "+l"(acc[r][0]) : "l"(xp), "l"(wp0));
                asm("fma.rn.f32x2 %0, %1, %2, %0;" : "+l"(acc[r][1]) : "l"(xp), "l"(wp1));
            }
        }
    }

    float4 bb = __ldg((const float4*)S.b + lane);
    #pragma unroll
    for (int r = 0; r < 8; r++) {
        int row = row0 + r0 + r;
        if (row >= N0) continue;
        float o0, o1, o2, o3;
        asm("mov.b64 {%0, %1}, %2;" : "=f"(o0), "=f"(o1) : "l"(acc[r][0]));
        asm("mov.b64 {%0, %1}, %2;" : "=f"(o2), "=f"(o3) : "l"(acc[r][1]));
        float4 o;
        o.x = fmaxf(o0 + bb.x, 0.f);
        o.y = fmaxf(o1 + bb.y, 0.f);
        o.z = fmaxf(o2 + bb.z, 0.f);
        o.w = fmaxf(o3 + bb.w, 0.f);
        *(float4*)(S.obase + (long long)row * (5 * DD) + lane * 4) = o;
    }
}

// ---------------- attention combine ----------------
__global__ void k_att(const float* __restrict__ attv, float* __restrict__ out) {
    int gt = blockIdx.x * blockDim.x + threadIdx.x;
    int n = gt >> 5;
    int lane = gt & 31;
    if (n >= N0) return;
    const float4* base = (const float4*)(g_allm + (long long)n * (5 * DD));
    float4 a[5];
    float sc[5];
    #pragma unroll
    for (int p = 0; p < 5; p++) {
        a[p] = base[p * 32 + lane];
        float4 av = __ldg((const float4*)attv + p * 32 + lane);
        float d = a[p].x * av.x + a[p].y * av.y + a[p].z * av.z + a[p].w * av.w;
        #pragma unroll
        for (int o = 16; o; o >>= 1) d += __shfl_xor_sync(0xFFFFFFFFu, d, o);
        sc[p] = d;
    }
    float m = sc[0];
    #pragma unroll
    for (int p = 1; p < 5; p++) m = fmaxf(m, sc[p]);
    float ssum = 0.f;
    #pragma unroll
    for (int p = 0; p < 5; p++) { sc[p] = __expf(sc[p] - m); ssum += sc[p]; }
    float inv = 1.0f / ssum;
    float4 o = make_float4(0.f, 0.f, 0.f, 0.f);
    #pragma unroll
    for (int p = 0; p < 5; p++) {
        float wgt = sc[p] * inv;
        o.x += wgt * a[p].x; o.y += wgt * a[p].y;
        o.z += wgt * a[p].z; o.w += wgt * a[p].w;
    }
    ((float4*)out)[(long long)n * 32 + lane] = o;
}

// ---------------- host orchestration ----------------
static inline GList mkl(const float* feat, const int* offs, const int* gi,
                        const float* gw, const float* xm, float* out,
                        int nrow, int blk0) {
    GList L; L.feat = feat; L.offs = offs; L.gi = gi; L.gw = gw;
    L.xm = xm; L.out = out; L.nrow = nrow; L.blk0 = blk0; return L;
}

extern "C" void kernel_launch(void* const* d_in, const int* in_sizes, int n_in,
                              void* d_out, int out_size) {
    const float* x_node = (const float*)d_in[0];
    const float* x1   = (const float*)d_in[1];
    const float* x2   = (const float*)d_in[2];
    const float* x3   = (const float*)d_in[3];
    const float* w1   = (const float*)d_in[4];
    const float* w2   = (const float*)d_in[5];
    const float* w3   = (const float*)d_in[6];
    const float* W1   = (const float*)d_in[7];
    const float* b1   = (const float*)d_in[8];
    const float* W2   = (const float*)d_in[9];
    const float* b2   = (const float*)d_in[10];
    const float* W3   = (const float*)d_in[11];
    const float* b3   = (const float*)d_in[12];
    const float* W121 = (const float*)d_in[13];
    const float* b121 = (const float*)d_in[14];
    const float* W131 = (const float*)d_in[15];
    const float* b131 = (const float*)d_in[16];
    const float* attv = (const float*)d_in[17];
    const int* e1s  = (const int*)d_in[18];
    const int* e1d  = (const int*)d_in[19];
    const int* e2s  = (const int*)d_in[20];
    const int* e2d  = (const int*)d_in[21];
    const int* e3s  = (const int*)d_in[22];
    const int* e3d  = (const int*)d_in[23];
    const int* e12s = (const int*)d_in[24];
    const int* e12d = (const int*)d_in[25];
    const int* e13s = (const int*)d_in[26];
    const int* e13d = (const int*)d_in[27];
    float* out = (float*)d_out;

    float *net1, *midB, *midC, *midD, *n3bD, *midE, *n3bE;
    float *sumA, *sumB, *sumC, *sumD, *sumE, *allm, *gw;
    int *cnt, *offs, *gi;
    cudaGetSymbolAddress((void**)&net1, g_net1);
    cudaGetSymbolAddress((void**)&midB, g_midB);
    cudaGetSymbolAddress((void**)&midC, g_midC);
    cudaGetSymbolAddress((void**)&midD, g_midD);
    cudaGetSymbolAddress((void**)&n3bD, g_n3bD);
    cudaGetSymbolAddress((void**)&midE, g_midE);
    cudaGetSymbolAddress((void**)&n3bE, g_n3bE);
    cudaGetSymbolAddress((void**)&sumA, g_sumA);
    cudaGetSymbolAddress((void**)&sumB, g_sumB);
    cudaGetSymbolAddress((void**)&sumC, g_sumC);
    cudaGetSymbolAddress((void**)&sumD, g_sumD);
    cudaGetSymbolAddress((void**)&sumE, g_sumE);
    cudaGetSymbolAddress((void**)&allm, g_allm);
    cudaGetSymbolAddress((void**)&cnt,  g_cnt);
    cudaGetSymbolAddress((void**)&offs, g_offs);
    cudaGetSymbolAddress((void**)&gi,   g_gi);
    cudaGetSymbolAddress((void**)&gw,   g_gw);

    cudaFuncSetAttribute(k_gemm_mega, cudaFuncAttributeMaxDynamicSharedMemorySize, GEMM_SMEM);

    static cudaStream_t s1 = nullptr;
    static cudaEvent_t evW1, evS1;
    if (!s1) {
        cudaStreamCreateWithFlags(&s1, cudaStreamNonBlocking);
        cudaEventCreateWithFlags(&evW1, cudaEventDisableTiming);
        cudaEventCreateWithFlags(&evS1, cudaEventDisableTiming);
    }

    const int T = 256;
    const int EB   = (NE + T - 1) / T;
    const int BM   = (NM + 7) / 8;   // blocks per NM-target list
    const int BN   = (N0 + 7) / 8;   // blocks per N0-target list

    // ================= CSR build (stream 0) =================
    cudaMemsetAsync(cnt, 0, TOTC * sizeof(int), 0);
    k_count<<<EB, T>>>(e1s, e1d, e2s, e2d, e3s, e3d, e12s, e12d, e13s, e13d);
    k_scan<<<10, 1024>>>();
    k_fill_all<<<EB, T>>>(e1s, e1d, e2s, e2d, e3s, e3d, e12s, e12d, e13s, e13d,
                          w1, w2, w3);

    // ===== Wave 1 (s0): first hops from x_node -> net1, midB, midC =====
    {
        GArgs ga; ga.nlists = 3;
        ga.l[0] = mkl(x_node, offs + OB_E1D, gi + GI_E1D, gw + GW_E1D, x1, net1, NM, 0);
        ga.l[1] = mkl(x_node, offs + OB_E2D, gi + GI_E2D, gw + GW_E2D, x2, midB, NM, BM);
        ga.l[2] = mkl(x_node, offs + OB_E3D, gi + GI_E3D, gw + GW_E3D, x3, midC, NM, 2 * BM);
        k_gather_mega<<<3 * BM, T>>>(ga);
    }
    cudaEventRecord(evW1, 0);

    // ===== s1: short-path second hops + their 3 GEMMs =====
    cudaStreamWaitEvent(s1, evW1, 0);
    {
        GArgs ga; ga.nlists = 3;
        ga.l[0] = mkl(net1, offs + OB_E1S, gi + GI_E1S, nullptr, nullptr, sumA, N0, 0);
        ga.l[1] = mkl(midB, offs + OB_E2S, gi + GI_E2S, nullptr, nullptr, sumB, N0, BN);
        ga.l[2] = mkl(midC, offs + OB_E3S, gi + GI_E3S, nullptr, nullptr, sumC, N0, 2 * BN);
        k_gather_mega<<<3 * BN, T, 0, s1>>>(ga);
    }
    {
        GemmArgs gg;
        gg.s[0] = {sumA, W1, b1, allm + 0 * DD};
        gg.s[1] = {sumB, W2, b2, allm + 1 * DD};
        gg.s[2] = {sumC, W3, b3, allm + 2 * DD};
        k_gemm_mega<<<3 * GBLK, T, GEMM_SMEM, s1>>>(gg);
    }
    cudaEventRecord(evS1, s1);

    // ===== s0: long paths =====
    {   // hop 2: net1 -> midD (x2), net1 -> midE (x3)
        GArgs ga; ga.nlists = 2;
        ga.l[0] = mkl(net1, offs + OB_E12D, gi + GI_E12D, nullptr, x2, midD, NM, 0);
        ga.l[1] = mkl(net1, offs + OB_E13D, gi + GI_E13D, nullptr, x3, midE, NM, BM);
        k_gather_mega<<<2 * BM, T>>>(ga);
    }
    {   // hop 3: midD -> n3bD (x1), midE -> n3bE (x1)
        GArgs ga; ga.nlists = 2;
        ga.l[0] = mkl(midD, offs + OB_E12S, gi + GI_E12S, nullptr, x1, n3bD, NM, 0);
        ga.l[1] = mkl(midE, offs + OB_E13S, gi + GI_E13S, nullptr, x1, n3bE, NM, BM);
        k_gather_mega<<<2 * BM, T>>>(ga);
    }
    {   // hop 4: weighted back to N0
        GArgs ga; ga.nlists = 2;
        ga.l[0] = mkl(n3bD, offs + OB_E1S, gi + GI_E1S, gw + GW_E1S, nullptr, sumD, N0, 0);
        ga.l[1] = mkl(n3bE, offs + OB_E1S, gi + GI_E1S, gw + GW_E1S, nullptr, sumE, N0, BN);
        k_gather_mega<<<2 * BN, T>>>(ga);
    }
    {
        GemmArgs gg;
        gg.s[0] = {sumD, W121, b121, allm + 3 * DD};
        gg.s[1] = {sumE, W131, b131, allm + 4 * DD};
        gg.s[2] = {sumD, W121, b121, allm + 3 * DD};  // unused (nseg via grid)
        k_gemm_mega<<<2 * GBLK, T, GEMM_SMEM>>>(gg);
    }

    // join + attention combine
    cudaStreamWaitEvent(0, evS1, 0);
    k_att<<<(N0 + 7) / 8, T>>>(attv, out);
}

// round 5
// speedup vs baseline: 1.7863x; 1.0242x over previous
#include <cuda_runtime.h>
#include <cstdint>

#define N0   50000
#define NM   25000
#define DD   128
#define NE   800000
#define NE12 400000

// ---------------- CSR list layout (10 lists) ----------------
#define B_E1D  0
#define B_E1S  (B_E1D + NM)
#define B_E2D  (B_E1S + N0)
#define B_E2S  (B_E2D + NM)
#define B_E3D  (B_E2S + N0)
#define B_E3S  (B_E3D + NM)
#define B_E12D (B_E3S + N0)
#define B_E12S (B_E12D + NM)
#define B_E13D (B_E12S + NM)
#define B_E13S (B_E13D + NM)
#define TOTC   (B_E13S + NM)

#define OB_E1D  0
#define OB_E1S  (OB_E1D + NM + 1)
#define OB_E2D  (OB_E1S + N0 + 1)
#define OB_E2S  (OB_E2D + NM + 1)
#define OB_E3D  (OB_E2S + N0 + 1)
#define OB_E3S  (OB_E3D + NM + 1)
#define OB_E12D (OB_E3S + N0 + 1)
#define OB_E12S (OB_E12D + NM + 1)
#define OB_E13D (OB_E12S + NM + 1)
#define OB_E13S (OB_E13D + NM + 1)
#define TOTO    (OB_E13S + NM + 1)

#define GI_E1D  0
#define GI_E1S  (GI_E1D + NE)
#define GI_E2D  (GI_E1S + NE)
#define GI_E2S  (GI_E2D + NE)
#define GI_E3D  (GI_E2S + NE)
#define GI_E3S  (GI_E3D + NE)
#define GI_E12D (GI_E3S + NE)
#define GI_E12S (GI_E12D + NE12)
#define GI_E13D (GI_E12S + NE12)
#define GI_E13S (GI_E13D + NE12)
#define TOTGI   (GI_E13S + NE12)

#define GW_E1D  0
#define GW_E1S  (GW_E1D + NE)
#define GW_E2D  (GW_E1S + NE)
#define GW_E3D  (GW_E2D + NE)
#define TOTGW   (GW_E3D + NE)

// ---------------- static device scratch ----------------
__device__ int   g_cnt[TOTC];
__device__ int   g_cur[TOTC];
__device__ int   g_offs[TOTO];
__device__ int   g_gi[TOTGI];
__device__ float g_gw[TOTGW];
__device__ float g_one[1] = {1.0f};

__device__ float g_net1[NM * DD];
__device__ float g_midB[NM * DD];
__device__ float g_midC[NM * DD];
__device__ float g_midD[NM * DD];
__device__ float g_n3bD[NM * DD];
__device__ float g_midE[NM * DD];
__device__ float g_n3bE[NM * DD];
__device__ float g_sumA[N0 * DD];
__device__ float g_sumB[N0 * DD];
__device__ float g_sumC[N0 * DD];
__device__ float g_sumD[N0 * DD];
__device__ float g_sumE[N0 * DD];
__device__ float g_allm[(long long)N0 * 5 * DD];

__constant__ int c_lbase[10] = {B_E1D,B_E1S,B_E2D,B_E2S,B_E3D,B_E3S,B_E12D,B_E12S,B_E13D,B_E13S};
__constant__ int c_obase[10] = {OB_E1D,OB_E1S,OB_E2D,OB_E2S,OB_E3D,OB_E3S,OB_E12D,OB_E12S,OB_E13D,OB_E13S};
__constant__ int c_ln[10]    = {NM,N0,NM,N0,NM,N0,NM,NM,NM,NM};

// ---------------- CSR build ----------------
__global__ void k_count(const int* __restrict__ e1s, const int* __restrict__ e1d,
                        const int* __restrict__ e2s, const int* __restrict__ e2d,
                        const int* __restrict__ e3s, const int* __restrict__ e3d,
                        const int* __restrict__ e12s, const int* __restrict__ e12d,
                        const int* __restrict__ e13s, const int* __restrict__ e13d) {
    int i = blockIdx.x * blockDim.x + threadIdx.x;
    if (i < NE) {
        atomicAdd(&g_cnt[B_E1D + e1d[i]], 1); atomicAdd(&g_cnt[B_E1S + e1s[i]], 1);
        atomicAdd(&g_cnt[B_E2D + e2d[i]], 1); atomicAdd(&g_cnt[B_E2S + e2s[i]], 1);
        atomicAdd(&g_cnt[B_E3D + e3d[i]], 1); atomicAdd(&g_cnt[B_E3S + e3s[i]], 1);
    }
    if (i < NE12) {
        atomicAdd(&g_cnt[B_E12D + e12d[i]], 1); atomicAdd(&g_cnt[B_E12S + e12s[i]], 1);
        atomicAdd(&g_cnt[B_E13D + e13d[i]], 1); atomicAdd(&g_cnt[B_E13S + e13s[i]], 1);
    }
}

__global__ void k_scan() {
    __shared__ int sh[1024];
    int b = blockIdx.x;
    int n  = c_ln[b];
    int cb = c_lbase[b];
    int ob = c_obase[b];
    int t = threadIdx.x;
    int chunk = (n + 1023) >> 10;
    int lo = t * chunk;
    int hi = lo + chunk; if (hi > n) hi = n; if (lo > n) lo = n;
    int s = 0;
    for (int i = lo; i < hi; i++) s += g_cnt[cb + i];
    sh[t] = s;
    __syncthreads();
    for (int d = 1; d < 1024; d <<= 1) {
        int v = (t >= d) ? sh[t - d] : 0;
        __syncthreads();
        sh[t] += v;
        __syncthreads();
    }
    int run = (t == 0) ? 0 : sh[t - 1];
    for (int i = lo; i < hi; i++) {
        g_offs[ob + i] = run;
        g_cur [cb + i] = run;
        run += g_cnt[cb + i];
    }
    if (t == 1023) g_offs[ob + n] = sh[1023];
}

__global__ void k_fill_all(const int* __restrict__ e1s, const int* __restrict__ e1d,
                           const int* __restrict__ e2s, const int* __restrict__ e2d,
                           const int* __restrict__ e3s, const int* __restrict__ e3d,
                           const int* __restrict__ e12s, const int* __restrict__ e12d,
                           const int* __restrict__ e13s, const int* __restrict__ e13d,
                           const float* __restrict__ w1, const float* __restrict__ w2,
                           const float* __restrict__ w3) {
    int e = blockIdx.x * blockDim.x + threadIdx.x;
    if (e < NE) {
        int a1 = __ldg(e1s + e), b1 = __ldg(e1d + e); float ww1 = __ldg(w1 + e);
        int a2 = __ldg(e2s + e), b2 = __ldg(e2d + e); float ww2 = __ldg(w2 + e);
        int a3 = __ldg(e3s + e), b3 = __ldg(e3d + e); float ww3 = __ldg(w3 + e);
        int p0 = atomicAdd(&g_cur[B_E1D + b1], 1);
        int p1 = atomicAdd(&g_cur[B_E1S + a1], 1);
        int p2 = atomicAdd(&g_cur[B_E2D + b2], 1);
        int p3 = atomicAdd(&g_cur[B_E2S + a2], 1);
        int p4 = atomicAdd(&g_cur[B_E3D + b3], 1);
        int p5 = atomicAdd(&g_cur[B_E3S + a3], 1);
        g_gi[GI_E1D + p0] = a1; g_gw[GW_E1D + p0] = ww1;
        g_gi[GI_E1S + p1] = b1; g_gw[GW_E1S + p1] = ww1;
        g_gi[GI_E2D + p2] = a2; g_gw[GW_E2D + p2] = ww2;
        g_gi[GI_E2S + p3] = b2;
        g_gi[GI_E3D + p4] = a3; g_gw[GW_E3D + p4] = ww3;
        g_gi[GI_E3S + p5] = b3;
    }
    if (e < NE12) {
        int a4 = __ldg(e12s + e), b4 = __ldg(e12d + e);
        int a5 = __ldg(e13s + e), b5 = __ldg(e13d + e);
        int p6 = atomicAdd(&g_cur[B_E12D + b4], 1);
        int p7 = atomicAdd(&g_cur[B_E12S + a4], 1);
        int p8 = atomicAdd(&g_cur[B_E13D + b5], 1);
        int p9 = atomicAdd(&g_cur[B_E13S + a5], 1);
        g_gi[GI_E12D + p6] = a4;
        g_gi[GI_E12S + p7] = b4;
        g_gi[GI_E13D + p8] = a5;
        g_gi[GI_E13S + p9] = b5;
    }
}

// ---------------- mega gather: up to 4 CSR lists per launch ----------------
struct GList {
    const float* feat;
    const int*   offs;
    const int*   gi;
    const float* gw;    // null -> unweighted
    const float* xm;    // null -> no combine
    float*       out;
    int          nrow;
    int          blk0;
};
struct GArgs { GList l[4]; int nlists; };

__global__ void __launch_bounds__(256) k_gather_mega(GArgs ga) {
    int li = 0;
    #pragma unroll
    for (int i = 1; i < 4; i++)
        if (i < ga.nlists && (int)blockIdx.x >= ga.l[i].blk0) li = i;
    const GList& L = ga.l[li];

    int n = (blockIdx.x - L.blk0) * 8 + (threadIdx.x >> 5);
    int lane = threadIdx.x & 31;
    if (n >= L.nrow) return;

    const float4* feat = (const float4*)L.feat;
    const int*    gi   = L.gi;
    const float*  gwp  = L.gw ? L.gw : g_one;
    const int     ws   = L.gw ? 1 : 0;
    int beg = __ldg(L.offs + n);
    int end = __ldg(L.offs + n + 1);

    float4 acc0 = make_float4(0.f, 0.f, 0.f, 0.f);
    float4 acc1 = acc0;
    int e = beg;
    for (; e + 8 <= end; e += 8) {
        int g0 = __ldg(gi + e + 0), g1 = __ldg(gi + e + 1);
        int g2 = __ldg(gi + e + 2), g3 = __ldg(gi + e + 3);
        int g4 = __ldg(gi + e + 4), g5 = __ldg(gi + e + 5);
        int g6 = __ldg(gi + e + 6), g7 = __ldg(gi + e + 7);
        float4 v0 = __ldg(feat + ((unsigned)g0 << 5) + lane);
        float4 v1 = __ldg(feat + ((unsigned)g1 << 5) + lane);
        float4 v2 = __ldg(feat + ((unsigned)g2 << 5) + lane);
        float4 v3 = __ldg(feat + ((unsigned)g3 << 5) + lane);
        float4 v4 = __ldg(feat + ((unsigned)g4 << 5) + lane);
        float4 v5 = __ldg(feat + ((unsigned)g5 << 5) + lane);
        float4 v6 = __ldg(feat + ((unsigned)g6 << 5) + lane);
        float4 v7 = __ldg(feat + ((unsigned)g7 << 5) + lane);
        float w0 = __ldg(gwp + (e + 0) * ws), w1 = __ldg(gwp + (e + 1) * ws);
        float w2 = __ldg(gwp + (e + 2) * ws), w3 = __ldg(gwp + (e + 3) * ws);
        float w4 = __ldg(gwp + (e + 4) * ws), w5 = __ldg(gwp + (e + 5) * ws);
        float w6 = __ldg(gwp + (e + 6) * ws), w7 = __ldg(gwp + (e + 7) * ws);
        acc0.x += v0.x*w0 + v2.x*w2 + v4.x*w4 + v6.x*w6;
        acc0.y += v0.y*w0 + v2.y*w2 + v4.y*w4 + v6.y*w6;
        acc0.z += v0.z*w0 + v2.z*w2 + v4.z*w4 + v6.z*w6;
        acc0.w += v0.w*w0 + v2.w*w2 + v4.w*w4 + v6.w*w6;
        acc1.x += v1.x*w1 + v3.x*w3 + v5.x*w5 + v7.x*w7;
        acc1.y += v1.y*w1 + v3.y*w3 + v5.y*w5 + v7.y*w7;
        acc1.z += v1.z*w1 + v3.z*w3 + v5.z*w5 + v7.z*w7;
        acc1.w += v1.w*w1 + v3.w*w3 + v5.w*w5 + v7.w*w7;
    }
    for (; e < end; e++) {
        int g = __ldg(gi + e);
        float4 v = __ldg(feat + ((unsigned)g << 5) + lane);
        float w = __ldg(gwp + e * ws);
        acc0.x += v.x * w; acc0.y += v.y * w; acc0.z += v.z * w; acc0.w += v.w * w;
    }
    float4 acc;
    acc.x = acc0.x + acc1.x; acc.y = acc0.y + acc1.y;
    acc.z = acc0.z + acc1.z; acc.w = acc0.w + acc1.w;
    int deg = end - beg;
    float r = 1.0f / (float)(deg < 1 ? 1 : deg);
    acc.x *= r; acc.y *= r; acc.z *= r; acc.w *= r;
    if (L.xm) {
        float4 x = __ldg((const float4*)L.xm + n * 32 + lane);
        acc.x = (acc.x + x.x) * 0.5f;
        acc.y = (acc.y + x.y) * 0.5f;
        acc.z = (acc.z + x.z) * 0.5f;
        acc.w = (acc.w + x.w) * 0.5f;
    }
    ((float4*)L.out)[n * 32 + lane] = acc;
}

// ---------------- fused hop4: one E1S walk, 3 sources -> 3 sums ----------------
__global__ void __launch_bounds__(256) k_hop4(const float* __restrict__ fA,   // net1 (unweighted)
                                              const float* __restrict__ fD,   // n3bD (*w)
                                              const float* __restrict__ fE,   // n3bE (*w)
                                              const int* __restrict__ offs,
                                              const int* __restrict__ gi,
                                              const float* __restrict__ gw,
                                              float* __restrict__ sA,
                                              float* __restrict__ sD,
                                              float* __restrict__ sE) {
    int n = blockIdx.x * 8 + (threadIdx.x >> 5);
    int lane = threadIdx.x & 31;
    if (n >= N0) return;
    int beg = __ldg(offs + n);
    int end = __ldg(offs + n + 1);
    const float4* A = (const float4*)fA;
    const float4* D = (const float4*)fD;
    const float4* E = (const float4*)fE;
    float4 aA = make_float4(0.f,0.f,0.f,0.f), aD = aA, aE = aA;
    int e = beg;
    for (; e + 2 <= end; e += 2) {
        int g0 = __ldg(gi + e), g1 = __ldg(gi + e + 1);
        float w0 = __ldg(gw + e), w1 = __ldg(gw + e + 1);
        unsigned o0 = ((unsigned)g0 << 5) + lane;
        unsigned o1 = ((unsigned)g1 << 5) + lane;
        float4 vA0 = __ldg(A + o0), vA1 = __ldg(A + o1);
        float4 vD0 = __ldg(D + o0), vD1 = __ldg(D + o1);
        float4 vE0 = __ldg(E + o0), vE1 = __ldg(E + o1);
        aA.x += vA0.x + vA1.x; aA.y += vA0.y + vA1.y;
        aA.z += vA0.z + vA1.z; aA.w += vA0.w + vA1.w;
        aD.x += vD0.x*w0 + vD1.x*w1; aD.y += vD0.y*w0 + vD1.y*w1;
        aD.z += vD0.z*w0 + vD1.z*w1; aD.w += vD0.w*w0 + vD1.w*w1;
        aE.x += vE0.x*w0 + vE1.x*w1; aE.y += vE0.y*w0 + vE1.y*w1;
        aE.z += vE0.z*w0 + vE1.z*w1; aE.w += vE0.w*w0 + vE1.w*w1;
    }
    if (e < end) {
        int g = __ldg(gi + e);
        float w = __ldg(gw + e);
        unsigned o = ((unsigned)g << 5) + lane;
        float4 vA = __ldg(A + o), vD = __ldg(D + o), vE = __ldg(E + o);
        aA.x += vA.x; aA.y += vA.y; aA.z += vA.z; aA.w += vA.w;
        aD.x += vD.x*w; aD.y += vD.y*w; aD.z += vD.z*w; aD.w += vD.w*w;
        aE.x += vE.x*w; aE.y += vE.y*w; aE.z += vE.z*w; aE.w += vE.w*w;
    }
    int deg = end - beg;
    float r = 1.0f / (float)(deg < 1 ? 1 : deg);
    aA.x *= r; aA.y *= r; aA.z *= r; aA.w *= r;
    aD.x *= r; aD.y *= r; aD.z *= r; aD.w *= r;
    aE.x *= r; aE.y *= r; aE.z *= r; aE.w *= r;
    unsigned oi = n * 32 + lane;
    ((float4*)sA)[oi] = aA;
    ((float4*)sD)[oi] = aD;
    ((float4*)sE)[oi] = aE;
}

// ---------------- tf32 tensor-core GEMM + bias + relu ----------------
// out[n, j] = relu(b[j] + sum_k sin[n,k] * W[j,k])
// 3-term tf32 split: acc = xh*Wh + xl*Wh + xh*Wl  (error ~2^-24)
#define GM   128
#define GP   132
#define GEMM_BLK ((N0 + GM - 1) / GM)
#define GEMM_SM_BYTES (3 * GM * GP * 4)

struct GemmSeg { const float* sin; const float* W; const float* b; float* obase; };
struct GemmArgs { GemmSeg s[3]; };

__device__ __forceinline__ uint32_t f2tf32(float x) {
    uint32_t r;
    asm("cvt.rna.tf32.f32 %0, %1;" : "=r"(r) : "f"(x));
    return r;
}

__device__ __forceinline__ void mma_tf32(float* c, const uint32_t* a,
                                         uint32_t b0, uint32_t b1) {
    asm("mma.sync.aligned.m16n8k8.row.col.f32.tf32.tf32.f32 "
        "{%0,%1,%2,%3}, {%4,%5,%6,%7}, {%8,%9}, {%0,%1,%2,%3};"
        : "+f"(c[0]), "+f"(c[1]), "+f"(c[2]), "+f"(c[3])
        : "r"(a[0]), "r"(a[1]), "r"(a[2]), "r"(a[3]), "r"(b0), "r"(b1));
}

__global__ void __launch_bounds__(256) k_gemm_tf32(GemmArgs gargs) {
    extern __shared__ float sh[];
    float* Whi = sh;                  // [j][k] pitch GP, tf32-hi of W
    float* Wlo = sh + GM * GP;        // tf32-lo residual
    float* xs  = sh + 2 * GM * GP;    // [r][k] pitch GP, fp32
    int tid = threadIdx.x;
    int seg = blockIdx.x / GEMM_BLK;
    int blk = blockIdx.x % GEMM_BLK;
    const GemmSeg S = gargs.s[seg];

    // load + split W
    for (int idx = tid; idx < DD * DD / 4; idx += 256) {
        int j = idx >> 5, k4 = (idx & 31) * 4;
        float4 w = __ldg((const float4*)S.W + idx);
        float4 hi, lo;
        hi.x = __uint_as_float(f2tf32(w.x)); lo.x = __uint_as_float(f2tf32(w.x - hi.x));
        hi.y = __uint_as_float(f2tf32(w.y)); lo.y = __uint_as_float(f2tf32(w.y - hi.y));
        hi.z = __uint_as_float(f2tf32(w.z)); lo.z = __uint_as_float(f2tf32(w.z - hi.z));
        hi.w = __uint_as_float(f2tf32(w.w)); lo.w = __uint_as_float(f2tf32(w.w - hi.w));
        *(float4*)(Whi + j * GP + k4) = hi;
        *(float4*)(Wlo + j * GP + k4) = lo;
    }
    // load x tile
    int row0 = blk * GM;
    for (int idx = tid; idx < GM * DD / 4; idx += 256) {
        int r = idx >> 5, k4 = (idx & 31) * 4;
        int row = row0 + r;
        float4 v = make_float4(0.f, 0.f, 0.f, 0.f);
        if (row < N0) v = __ldg((const float4*)S.sin + (long long)row * 32 + (idx & 31));
        *(float4*)(xs + r * GP + k4) = v;
    }
    __syncthreads();

    int warp = tid >> 5, lane = tid & 31;
    int rw = warp * 16 + (lane >> 2);     // A row for a0/a2
    int kk = lane & 3;
    float acc[16][4];
    #pragma unroll
    for (int t = 0; t < 16; t++) {
        acc[t][0] = 0.f; acc[t][1] = 0.f; acc[t][2] = 0.f; acc[t][3] = 0.f;
    }

    const float* bhp = Whi + (lane >> 2) * GP + kk;
    const float* blp = Wlo + (lane >> 2) * GP + kk;

    #pragma unroll 1
    for (int ks = 0; ks < 16; ks++) {
        int k0 = ks * 8;
        float x0 = xs[rw * GP + k0 + kk];
        float x1 = xs[(rw + 8) * GP + k0 + kk];
        float x2 = xs[rw * GP + k0 + kk + 4];
        float x3 = xs[(rw + 8) * GP + k0 + kk + 4];
        uint32_t ah[4], al[4];
        ah[0] = f2tf32(x0); al[0] = f2tf32(x0 - __uint_as_float(ah[0]));
        ah[1] = f2tf32(x1); al[1] = f2tf32(x1 - __uint_as_float(ah[1]));
        ah[2] = f2tf32(x2); al[2] = f2tf32(x2 - __uint_as_float(ah[2]));
        ah[3] = f2tf32(x3); al[3] = f2tf32(x3 - __uint_as_float(ah[3]));
        #pragma unroll
        for (int t = 0; t < 16; t++) {
            int off = t * 8 * GP + k0;
            uint32_t bh0 = __float_as_uint(bhp[off]);
            uint32_t bh1 = __float_as_uint(bhp[off + 4]);
            uint32_t bl0 = __float_as_uint(blp[off]);
            uint32_t bl1 = __float_as_uint(blp[off + 4]);
            mma_tf32(acc[t], ah, bh0, bh1);
            mma_tf32(acc[t], al, bh0, bh1);
            mma_tf32(acc[t], ah, bl0, bl1);
        }
    }

    // epilogue: bias + relu, rows rw_g and rw_g+8, cols j, j+1 per tile
    int jb = 2 * (lane & 3);
    int rg = row0 + warp * 16 + (lane >> 2);
    #pragma unroll
    for (int t = 0; t < 16; t++) {
        int j = t * 8 + jb;
        float2 bb = __ldg((const float2*)(S.b + j));
        if (rg < N0) {
            float2 o;
            o.x = fmaxf(acc[t][0] + bb.x, 0.f);
            o.y = fmaxf(acc[t][1] + bb.y, 0.f);
            *(float2*)(S.obase + (long long)rg * (5 * DD) + j) = o;
        }
        if (rg + 8 < N0) {
            float2 o;
            o.x = fmaxf(acc[t][2] + bb.x, 0.f);
            o.y = fmaxf(acc[t][3] + bb.y, 0.f);
            *(float2*)(S.obase + (long long)(rg + 8) * (5 * DD) + j) = o;
        }
    }
}

// ---------------- attention combine ----------------
__global__ void k_att(const float* __restrict__ attv, float* __restrict__ out) {
    int gt = blockIdx.x * blockDim.x + threadIdx.x;
    int n = gt >> 5;
    int lane = gt & 31;
    if (n >= N0) return;
    const float4* base = (const float4*)(g_allm + (long long)n * (5 * DD));
    float4 a[5];
    float sc[5];
    #pragma unroll
    for (int p = 0; p < 5; p++) {
        a[p] = base[p * 32 + lane];
        float4 av = __ldg((const float4*)attv + p * 32 + lane);
        float d = a[p].x * av.x + a[p].y * av.y + a[p].z * av.z + a[p].w * av.w;
        #pragma unroll
        for (int o = 16; o; o >>= 1) d += __shfl_xor_sync(0xFFFFFFFFu, d, o);
        sc[p] = d;
    }
    float m = sc[0];
    #pragma unroll
    for (int p = 1; p < 5; p++) m = fmaxf(m, sc[p]);
    float ssum = 0.f;
    #pragma unroll
    for (int p = 0; p < 5; p++) { sc[p] = __expf(sc[p] - m); ssum += sc[p]; }
    float inv = 1.0f / ssum;
    float4 o = make_float4(0.f, 0.f, 0.f, 0.f);
    #pragma unroll
    for (int p = 0; p < 5; p++) {
        float wgt = sc[p] * inv;
        o.x += wgt * a[p].x; o.y += wgt * a[p].y;
        o.z += wgt * a[p].z; o.w += wgt * a[p].w;
    }
    ((float4*)out)[(long long)n * 32 + lane] = o;
}

// ---------------- host orchestration ----------------
static inline GList mkl(const float* feat, const int* offs, const int* gi,
                        const float* gw, const float* xm, float* out,
                        int nrow, int blk0) {
    GList L; L.feat = feat; L.offs = offs; L.gi = gi; L.gw = gw;
    L.xm = xm; L.out = out; L.nrow = nrow; L.blk0 = blk0; return L;
}

extern "C" void kernel_launch(void* const* d_in, const int* in_sizes, int n_in,
                              void* d_out, int out_size) {
    const float* x_node = (const float*)d_in[0];
    const float* x1   = (const float*)d_in[1];
    const float* x2   = (const float*)d_in[2];
    const float* x3   = (const float*)d_in[3];
    const float* w1   = (const float*)d_in[4];
    const float* w2   = (const float*)d_in[5];
    const float* w3   = (const float*)d_in[6];
    const float* W1   = (const float*)d_in[7];
    const float* b1   = (const float*)d_in[8];
    const float* W2   = (const float*)d_in[9];
    const float* b2   = (const float*)d_in[10];
    const float* W3   = (const float*)d_in[11];
    const float* b3   = (const float*)d_in[12];
    const float* W121 = (const float*)d_in[13];
    const float* b121 = (const float*)d_in[14];
    const float* W131 = (const float*)d_in[15];
    const float* b131 = (const float*)d_in[16];
    const float* attv = (const float*)d_in[17];
    const int* e1s  = (const int*)d_in[18];
    const int* e1d  = (const int*)d_in[19];
    const int* e2s  = (const int*)d_in[20];
    const int* e2d  = (const int*)d_in[21];
    const int* e3s  = (const int*)d_in[22];
    const int* e3d  = (const int*)d_in[23];
    const int* e12s = (const int*)d_in[24];
    const int* e12d = (const int*)d_in[25];
    const int* e13s = (const int*)d_in[26];
    const int* e13d = (const int*)d_in[27];
    float* out = (float*)d_out;

    float *net1, *midB, *midC, *midD, *n3bD, *midE, *n3bE;
    float *sumA, *sumB, *sumC, *sumD, *sumE, *allm, *gw;
    int *cnt, *offs, *gi;
    cudaGetSymbolAddress((void**)&net1, g_net1);
    cudaGetSymbolAddress((void**)&midB, g_midB);
    cudaGetSymbolAddress((void**)&midC, g_midC);
    cudaGetSymbolAddress((void**)&midD, g_midD);
    cudaGetSymbolAddress((void**)&n3bD, g_n3bD);
    cudaGetSymbolAddress((void**)&midE, g_midE);
    cudaGetSymbolAddress((void**)&n3bE, g_n3bE);
    cudaGetSymbolAddress((void**)&sumA, g_sumA);
    cudaGetSymbolAddress((void**)&sumB, g_sumB);
    cudaGetSymbolAddress((void**)&sumC, g_sumC);
    cudaGetSymbolAddress((void**)&sumD, g_sumD);
    cudaGetSymbolAddress((void**)&sumE, g_sumE);
    cudaGetSymbolAddress((void**)&allm, g_allm);
    cudaGetSymbolAddress((void**)&cnt,  g_cnt);
    cudaGetSymbolAddress((void**)&offs, g_offs);
    cudaGetSymbolAddress((void**)&gi,   g_gi);
    cudaGetSymbolAddress((void**)&gw,   g_gw);

    cudaFuncSetAttribute(k_gemm_tf32, cudaFuncAttributeMaxDynamicSharedMemorySize,
                         GEMM_SM_BYTES);

    static cudaStream_t s1 = nullptr;
    static cudaEvent_t evW1, evS1;
    if (!s1) {
        cudaStreamCreateWithFlags(&s1, cudaStreamNonBlocking);
        cudaEventCreateWithFlags(&evW1, cudaEventDisableTiming);
        cudaEventCreateWithFlags(&evS1, cudaEventDisableTiming);
    }

    const int T  = 256;
    const int EB = (NE + T - 1) / T;
    const int BM = (NM + 7) / 8;
    const int BN = (N0 + 7) / 8;

    // ================= CSR build (stream 0) =================
    cudaMemsetAsync(cnt, 0, TOTC * sizeof(int), 0);
    k_count<<<EB, T>>>(e1s, e1d, e2s, e2d, e3s, e3d, e12s, e12d, e13s, e13d);
    k_scan<<<10, 1024>>>();
    k_fill_all<<<EB, T>>>(e1s, e1d, e2s, e2d, e3s, e3d, e12s, e12d, e13s, e13d,
                          w1, w2, w3);

    // ===== Wave 1 (s0): first hops from x_node -> net1, midB, midC =====
    {
        GArgs ga; ga.nlists = 3;
        ga.l[0] = mkl(x_node, offs + OB_E1D, gi + GI_E1D, gw + GW_E1D, x1, net1, NM, 0);
        ga.l[1] = mkl(x_node, offs + OB_E2D, gi + GI_E2D, gw + GW_E2D, x2, midB, NM, BM);
        ga.l[2] = mkl(x_node, offs + OB_E3D, gi + GI_E3D, gw + GW_E3D, x3, midC, NM, 2 * BM);
        k_gather_mega<<<3 * BM, T>>>(ga);
    }
    cudaEventRecord(evW1, 0);

    // ===== s1: short paths 2,3 second hop + GEMMs =====
    cudaStreamWaitEvent(s1, evW1, 0);
    {
        GArgs ga; ga.nlists = 2;
        ga.l[0] = mkl(midB, offs + OB_E2S, gi + GI_E2S, nullptr, nullptr, sumB, N0, 0);
        ga.l[1] = mkl(midC, offs + OB_E3S, gi + GI_E3S, nullptr, nullptr, sumC, N0, BN);
        k_gather_mega<<<2 * BN, T, 0, s1>>>(ga);
    }
    {
        GemmArgs gg;
        gg.s[0] = {sumB, W2, b2, allm + 1 * DD};
        gg.s[1] = {sumC, W3, b3, allm + 2 * DD};
        gg.s[2] = {sumB, W2, b2, allm + 1 * DD};  // unused (grid covers 2 segs)
        k_gemm_tf32<<<2 * GEMM_BLK, T, GEMM_SM_BYTES, s1>>>(gg);
    }
    cudaEventRecord(evS1, s1);

    // ===== s0: long paths hop2, hop3, fused hop4 =====
    {
        GArgs ga; ga.nlists = 2;
        ga.l[0] = mkl(net1, offs + OB_E12D, gi + GI_E12D, nullptr, x2, midD, NM, 0);
        ga.l[1] = mkl(net1, offs + OB_E13D, gi + GI_E13D, nullptr, x3, midE, NM, BM);
        k_gather_mega<<<2 * BM, T>>>(ga);
    }
    {
        GArgs ga; ga.nlists = 2;
        ga.l[0] = mkl(midD, offs + OB_E12S, gi + GI_E12S, nullptr, x1, n3bD, NM, 0);
        ga.l[1] = mkl(midE, offs + OB_E13S, gi + GI_E13S, nullptr, x1, n3bE, NM, BM);
        k_gather_mega<<<2 * BM, T>>>(ga);
    }
    k_hop4<<<BN, T>>>(net1, n3bD, n3bE, offs + OB_E1S, gi + GI_E1S, gw + GW_E1S,
                      sumA, sumD, sumE);
    {
        GemmArgs gg;
        gg.s[0] = {sumA, W1, b1, allm + 0 * DD};
        gg.s[1] = {sumD, W121, b121, allm + 3 * DD};
        gg.s[2] = {sumE, W131, b131, allm + 4 * DD};
        k_gemm_tf32<<<3 * GEMM_BLK, T, GEMM_SM_BYTES>>>(gg);
    }

    // join + attention combine
    cudaStreamWaitEvent(0, evS1, 0);
    k_att<<<(N0 + 7) / 8, T>>>(attv, out);
}

// round 6
// speedup vs baseline: 1.9367x; 1.0842x over previous
#include <cuda_runtime.h>
#include <cuda_fp16.h>
#include <cstdint>

#define N0   50000
#define NM   25000
#define DD   128
#define NE   800000
#define NE12 400000

// ---------------- CSR list layout (10 lists) ----------------
#define B_E1D  0
#define B_E1S  (B_E1D + NM)
#define B_E2D  (B_E1S + N0)
#define B_E2S  (B_E2D + NM)
#define B_E3D  (B_E2S + N0)
#define B_E3S  (B_E3D + NM)
#define B_E12D (B_E3S + N0)
#define B_E12S (B_E12D + NM)
#define B_E13D (B_E12S + NM)
#define B_E13S (B_E13D + NM)
#define TOTC   (B_E13S + NM)

#define OB_E1D  0
#define OB_E1S  (OB_E1D + NM + 1)
#define OB_E2D  (OB_E1S + N0 + 1)
#define OB_E2S  (OB_E2D + NM + 1)
#define OB_E3D  (OB_E2S + N0 + 1)
#define OB_E3S  (OB_E3D + NM + 1)
#define OB_E12D (OB_E3S + N0 + 1)
#define OB_E12S (OB_E12D + NM + 1)
#define OB_E13D (OB_E12S + NM + 1)
#define OB_E13S (OB_E13D + NM + 1)
#define TOTO    (OB_E13S + NM + 1)

#define GI_E1D  0
#define GI_E1S  (GI_E1D + NE)
#define GI_E2D  (GI_E1S + NE)
#define GI_E2S  (GI_E2D + NE)
#define GI_E3D  (GI_E2S + NE)
#define GI_E3S  (GI_E3D + NE)
#define GI_E12D (GI_E3S + NE)
#define GI_E12S (GI_E12D + NE12)
#define GI_E13D (GI_E12S + NE12)
#define GI_E13S (GI_E13D + NE12)
#define TOTGI   (GI_E13S + NE12)

#define GW_E1D  0
#define GW_E1S  (GW_E1D + NE)
#define GW_E2D  (GW_E1S + NE)
#define GW_E3D  (GW_E2D + NE)
#define TOTGW   (GW_E3D + NE)

// ---------------- static device scratch ----------------
__device__ int    g_cnt[TOTC];
__device__ int    g_cur[TOTC];
__device__ int    g_offs[TOTO];
__device__ int    g_gi[TOTGI];
__device__ float  g_gw[TOTGW];

__device__ __half g_xn16[(long long)N0 * DD];
__device__ __half g_net1[NM * DD];
__device__ __half g_midB[NM * DD];
__device__ __half g_midC[NM * DD];
__device__ __half g_midD[NM * DD];
__device__ __half g_n3bD[NM * DD];
__device__ __half g_midE[NM * DD];
__device__ __half g_n3bE[NM * DD];
__device__ __half g_sumA[(long long)N0 * DD];
__device__ __half g_sumB[(long long)N0 * DD];
__device__ __half g_sumC[(long long)N0 * DD];
__device__ __half g_sumD[(long long)N0 * DD];
__device__ __half g_sumE[(long long)N0 * DD];
__device__ float  g_allm[(long long)N0 * 5 * DD];

__constant__ int c_lbase[10] = {B_E1D,B_E1S,B_E2D,B_E2S,B_E3D,B_E3S,B_E12D,B_E12S,B_E13D,B_E13S};
__constant__ int c_obase[10] = {OB_E1D,OB_E1S,OB_E2D,OB_E2S,OB_E3D,OB_E3S,OB_E12D,OB_E12S,OB_E13D,OB_E13S};
__constant__ int c_ln[10]    = {NM,N0,NM,N0,NM,N0,NM,NM,NM,NM};

// ---------------- fp16 helpers ----------------
__device__ __forceinline__ void acc4w(float4& a, uint2 v, float w) {
    float2 p = __half22float2(*(__half2*)&v.x);
    float2 q = __half22float2(*(__half2*)&v.y);
    a.x += p.x * w; a.y += p.y * w; a.z += q.x * w; a.w += q.y * w;
}
__device__ __forceinline__ void acc4(float4& a, uint2 v) {
    float2 p = __half22float2(*(__half2*)&v.x);
    float2 q = __half22float2(*(__half2*)&v.y);
    a.x += p.x; a.y += p.y; a.z += q.x; a.w += q.y;
}
__device__ __forceinline__ uint2 pack4(float4 a) {
    __half2 h0 = __floats2half2_rn(a.x, a.y);
    __half2 h1 = __floats2half2_rn(a.z, a.w);
    uint2 r; r.x = *(unsigned*)&h0; r.y = *(unsigned*)&h1; return r;
}

// ---------------- CSR build ----------------
__global__ void k_count(const int* __restrict__ e1s, const int* __restrict__ e1d,
                        const int* __restrict__ e2s, const int* __restrict__ e2d,
                        const int* __restrict__ e3s, const int* __restrict__ e3d,
                        const int* __restrict__ e12s, const int* __restrict__ e12d,
                        const int* __restrict__ e13s, const int* __restrict__ e13d) {
    int i = blockIdx.x * blockDim.x + threadIdx.x;
    if (i < NE) {
        atomicAdd(&g_cnt[B_E1D + e1d[i]], 1); atomicAdd(&g_cnt[B_E1S + e1s[i]], 1);
        atomicAdd(&g_cnt[B_E2D + e2d[i]], 1); atomicAdd(&g_cnt[B_E2S + e2s[i]], 1);
        atomicAdd(&g_cnt[B_E3D + e3d[i]], 1); atomicAdd(&g_cnt[B_E3S + e3s[i]], 1);
    }
    if (i < NE12) {
        atomicAdd(&g_cnt[B_E12D + e12d[i]], 1); atomicAdd(&g_cnt[B_E12S + e12s[i]], 1);
        atomicAdd(&g_cnt[B_E13D + e13d[i]], 1); atomicAdd(&g_cnt[B_E13S + e13s[i]], 1);
    }
}

__global__ void k_scan() {
    __shared__ int sh[1024];
    int b = blockIdx.x;
    int n  = c_ln[b];
    int cb = c_lbase[b];
    int ob = c_obase[b];
    int t = threadIdx.x;
    int chunk = (n + 1023) >> 10;
    int lo = t * chunk;
    int hi = lo + chunk; if (hi > n) hi = n; if (lo > n) lo = n;
    int s = 0;
    for (int i = lo; i < hi; i++) s += g_cnt[cb + i];
    sh[t] = s;
    __syncthreads();
    for (int d = 1; d < 1024; d <<= 1) {
        int v = (t >= d) ? sh[t - d] : 0;
        __syncthreads();
        sh[t] += v;
        __syncthreads();
    }
    int run = (t == 0) ? 0 : sh[t - 1];
    for (int i = lo; i < hi; i++) {
        g_offs[ob + i] = run;
        g_cur [cb + i] = run;
        run += g_cnt[cb + i];
    }
    if (t == 1023) g_offs[ob + n] = sh[1023];
}

__global__ void k_fill_all(const int* __restrict__ e1s, const int* __restrict__ e1d,
                           const int* __restrict__ e2s, const int* __restrict__ e2d,
                           const int* __restrict__ e3s, const int* __restrict__ e3d,
                           const int* __restrict__ e12s, const int* __restrict__ e12d,
                           const int* __restrict__ e13s, const int* __restrict__ e13d,
                           const float* __restrict__ w1, const float* __restrict__ w2,
                           const float* __restrict__ w3) {
    int e = blockIdx.x * blockDim.x + threadIdx.x;
    if (e < NE) {
        int a1 = __ldg(e1s + e), b1 = __ldg(e1d + e); float ww1 = __ldg(w1 + e);
        int a2 = __ldg(e2s + e), b2 = __ldg(e2d + e); float ww2 = __ldg(w2 + e);
        int a3 = __ldg(e3s + e), b3 = __ldg(e3d + e); float ww3 = __ldg(w3 + e);
        int p0 = atomicAdd(&g_cur[B_E1D + b1], 1);
        int p1 = atomicAdd(&g_cur[B_E1S + a1], 1);
        int p2 = atomicAdd(&g_cur[B_E2D + b2], 1);
        int p3 = atomicAdd(&g_cur[B_E2S + a2], 1);
        int p4 = atomicAdd(&g_cur[B_E3D + b3], 1);
        int p5 = atomicAdd(&g_cur[B_E3S + a3], 1);
        g_gi[GI_E1D + p0] = a1; g_gw[GW_E1D + p0] = ww1;
        g_gi[GI_E1S + p1] = b1; g_gw[GW_E1S + p1] = ww1;
        g_gi[GI_E2D + p2] = a2; g_gw[GW_E2D + p2] = ww2;
        g_gi[GI_E2S + p3] = b2;
        g_gi[GI_E3D + p4] = a3; g_gw[GW_E3D + p4] = ww3;
        g_gi[GI_E3S + p5] = b3;
    }
    if (e < NE12) {
        int a4 = __ldg(e12s + e), b4 = __ldg(e12d + e);
        int a5 = __ldg(e13s + e), b5 = __ldg(e13d + e);
        int p6 = atomicAdd(&g_cur[B_E12D + b4], 1);
        int p7 = atomicAdd(&g_cur[B_E12S + a4], 1);
        int p8 = atomicAdd(&g_cur[B_E13D + b5], 1);
        int p9 = atomicAdd(&g_cur[B_E13S + a5], 1);
        g_gi[GI_E12D + p6] = a4;
        g_gi[GI_E12S + p7] = b4;
        g_gi[GI_E13D + p8] = a5;
        g_gi[GI_E13S + p9] = b5;
    }
}

// ---------------- x_node fp32 -> fp16 ----------------
__global__ void k_cvt(const float* __restrict__ x, __half* __restrict__ y) {
    int i = blockIdx.x * blockDim.x + threadIdx.x;   // float4 index
    if (i >= N0 * 32) return;
    float4 v = __ldg((const float4*)x + i);
    ((uint2*)y)[i] = pack4(v);
}

// ---------------- mega gather (fp16 rows) ----------------
struct GList {
    const __half* feat;
    const int*    offs;
    const int*    gi;
    const float*  gw;
    const float*  xm;    // fp32, null -> no combine
    __half*       out;
    int           nrow;
    int           blk0;
};
struct GArgs { GList l[4]; int nlists; };

template<bool HASW, bool COMBINE>
__global__ void __launch_bounds__(256) k_gather16(GArgs ga) {
    int li = 0;
    #pragma unroll
    for (int i = 1; i < 4; i++)
        if (i < ga.nlists && (int)blockIdx.x >= ga.l[i].blk0) li = i;
    const GList& L = ga.l[li];

    int n = (blockIdx.x - L.blk0) * 8 + (threadIdx.x >> 5);
    int lane = threadIdx.x & 31;
    if (n >= L.nrow) return;

    const uint2* feat = (const uint2*)L.feat;
    const int*   gi   = L.gi;
    const float* gw   = L.gw;
    int beg = __ldg(L.offs + n);
    int end = __ldg(L.offs + n + 1);

    float4 a0 = make_float4(0.f, 0.f, 0.f, 0.f);
    float4 a1 = a0;
    int e = beg;
    for (; e + 8 <= end; e += 8) {
        int g0 = __ldg(gi + e + 0), g1 = __ldg(gi + e + 1);
        int g2 = __ldg(gi + e + 2), g3 = __ldg(gi + e + 3);
        int g4 = __ldg(gi + e + 4), g5 = __ldg(gi + e + 5);
        int g6 = __ldg(gi + e + 6), g7 = __ldg(gi + e + 7);
        uint2 v0 = __ldg(feat + ((unsigned)g0 << 5) + lane);
        uint2 v1 = __ldg(feat + ((unsigned)g1 << 5) + lane);
        uint2 v2 = __ldg(feat + ((unsigned)g2 << 5) + lane);
        uint2 v3 = __ldg(feat + ((unsigned)g3 << 5) + lane);
        uint2 v4 = __ldg(feat + ((unsigned)g4 << 5) + lane);
        uint2 v5 = __ldg(feat + ((unsigned)g5 << 5) + lane);
        uint2 v6 = __ldg(feat + ((unsigned)g6 << 5) + lane);
        uint2 v7 = __ldg(feat + ((unsigned)g7 << 5) + lane);
        if (HASW) {
            float w0 = __ldg(gw + e + 0), w1 = __ldg(gw + e + 1);
            float w2 = __ldg(gw + e + 2), w3 = __ldg(gw + e + 3);
            float w4 = __ldg(gw + e + 4), w5 = __ldg(gw + e + 5);
            float w6 = __ldg(gw + e + 6), w7 = __ldg(gw + e + 7);
            acc4w(a0, v0, w0); acc4w(a1, v1, w1);
            acc4w(a0, v2, w2); acc4w(a1, v3, w3);
            acc4w(a0, v4, w4); acc4w(a1, v5, w5);
            acc4w(a0, v6, w6); acc4w(a1, v7, w7);
        } else {
            acc4(a0, v0); acc4(a1, v1); acc4(a0, v2); acc4(a1, v3);
            acc4(a0, v4); acc4(a1, v5); acc4(a0, v6); acc4(a1, v7);
        }
    }
    for (; e < end; e++) {
        int g = __ldg(gi + e);
        uint2 v = __ldg(feat + ((unsigned)g << 5) + lane);
        if (HASW) acc4w(a0, v, __ldg(gw + e));
        else      acc4(a0, v);
    }
    float4 acc;
    acc.x = a0.x + a1.x; acc.y = a0.y + a1.y;
    acc.z = a0.z + a1.z; acc.w = a0.w + a1.w;
    int deg = end - beg;
    float r = 1.0f / (float)(deg < 1 ? 1 : deg);
    acc.x *= r; acc.y *= r; acc.z *= r; acc.w *= r;
    if (COMBINE) {
        float4 x = __ldg((const float4*)L.xm + n * 32 + lane);
        acc.x = (acc.x + x.x) * 0.5f;
        acc.y = (acc.y + x.y) * 0.5f;
        acc.z = (acc.z + x.z) * 0.5f;
        acc.w = (acc.w + x.w) * 0.5f;
    }
    ((uint2*)L.out)[n * 32 + lane] = pack4(acc);
}

// ---------------- fused hop4: one E1S walk, 3 fp16 sources -> 3 fp16 sums ----------------
__global__ void __launch_bounds__(256) k_hop4(const __half* __restrict__ fA,
                                              const __half* __restrict__ fD,
                                              const __half* __restrict__ fE,
                                              const int* __restrict__ offs,
                                              const int* __restrict__ gi,
                                              const float* __restrict__ gw,
                                              __half* __restrict__ sA,
                                              __half* __restrict__ sD,
                                              __half* __restrict__ sE) {
    int n = blockIdx.x * 8 + (threadIdx.x >> 5);
    int lane = threadIdx.x & 31;
    if (n >= N0) return;
    int beg = __ldg(offs + n);
    int end = __ldg(offs + n + 1);
    const uint2* A = (const uint2*)fA;
    const uint2* D = (const uint2*)fD;
    const uint2* E = (const uint2*)fE;
    float4 aA = make_float4(0.f,0.f,0.f,0.f), aD = aA, aE = aA;
    int e = beg;
    for (; e + 4 <= end; e += 4) {
        int g0 = __ldg(gi + e + 0), g1 = __ldg(gi + e + 1);
        int g2 = __ldg(gi + e + 2), g3 = __ldg(gi + e + 3);
        float w0 = __ldg(gw + e + 0), w1 = __ldg(gw + e + 1);
        float w2 = __ldg(gw + e + 2), w3 = __ldg(gw + e + 3);
        unsigned o0 = ((unsigned)g0 << 5) + lane;
        unsigned o1 = ((unsigned)g1 << 5) + lane;
        unsigned o2 = ((unsigned)g2 << 5) + lane;
        unsigned o3 = ((unsigned)g3 << 5) + lane;
        uint2 vA0 = __ldg(A + o0), vA1 = __ldg(A + o1), vA2 = __ldg(A + o2), vA3 = __ldg(A + o3);
        uint2 vD0 = __ldg(D + o0), vD1 = __ldg(D + o1), vD2 = __ldg(D + o2), vD3 = __ldg(D + o3);
        uint2 vE0 = __ldg(E + o0), vE1 = __ldg(E + o1), vE2 = __ldg(E + o2), vE3 = __ldg(E + o3);
        acc4(aA, vA0); acc4(aA, vA1); acc4(aA, vA2); acc4(aA, vA3);
        acc4w(aD, vD0, w0); acc4w(aD, vD1, w1); acc4w(aD, vD2, w2); acc4w(aD, vD3, w3);
        acc4w(aE, vE0, w0); acc4w(aE, vE1, w1); acc4w(aE, vE2, w2); acc4w(aE, vE3, w3);
    }
    for (; e < end; e++) {
        int g = __ldg(gi + e);
        float w = __ldg(gw + e);
        unsigned o = ((unsigned)g << 5) + lane;
        acc4(aA, __ldg(A + o));
        acc4w(aD, __ldg(D + o), w);
        acc4w(aE, __ldg(E + o), w);
    }
    int deg = end - beg;
    float r = 1.0f / (float)(deg < 1 ? 1 : deg);
    aA.x *= r; aA.y *= r; aA.z *= r; aA.w *= r;
    aD.x *= r; aD.y *= r; aD.z *= r; aD.w *= r;
    aE.x *= r; aE.y *= r; aE.z *= r; aE.w *= r;
    unsigned oi = n * 32 + lane;
    ((uint2*)sA)[oi] = pack4(aA);
    ((uint2*)sD)[oi] = pack4(aD);
    ((uint2*)sE)[oi] = pack4(aE);
}

// ---------------- tf32 tensor-core GEMM + bias + relu (fp16 input) ----------------
// x is fp16 (exactly representable in tf32) -> only W needs hi/lo split: 2 MMA terms.
#define GM   128
#define GP   132
#define GEMM_BLK ((N0 + GM - 1) / GM)
#define GEMM_SM_BYTES (3 * GM * GP * 4)

struct GemmSeg { const __half* sin; const float* W; const float* b; float* obase; };
struct GemmArgs { GemmSeg s[3]; };

__device__ __forceinline__ uint32_t f2tf32(float x) {
    uint32_t r;
    asm("cvt.rna.tf32.f32 %0, %1;" : "=r"(r) : "f"(x));
    return r;
}

__device__ __forceinline__ void mma_tf32(float* c, const uint32_t* a,
                                         uint32_t b0, uint32_t b1) {
    asm("mma.sync.aligned.m16n8k8.row.col.f32.tf32.tf32.f32 "
        "{%0,%1,%2,%3}, {%4,%5,%6,%7}, {%8,%9}, {%0,%1,%2,%3};"
        : "+f"(c[0]), "+f"(c[1]), "+f"(c[2]), "+f"(c[3])
        : "r"(a[0]), "r"(a[1]), "r"(a[2]), "r"(a[3]), "r"(b0), "r"(b1));
}

__global__ void __launch_bounds__(256) k_gemm_tf32(GemmArgs gargs) {
    extern __shared__ float sh[];
    float* Whi = sh;                  // [j][k] pitch GP
    float* Wlo = sh + GM * GP;
    float* xs  = sh + 2 * GM * GP;    // [r][k] pitch GP
    int tid = threadIdx.x;
    int seg = blockIdx.x / GEMM_BLK;
    int blk = blockIdx.x % GEMM_BLK;
    const GemmSeg S = gargs.s[seg];

    for (int idx = tid; idx < DD * DD / 4; idx += 256) {
        int j = idx >> 5, k4 = (idx & 31) * 4;
        float4 w = __ldg((const float4*)S.W + idx);
        float4 hi, lo;
        hi.x = __uint_as_float(f2tf32(w.x)); lo.x = __uint_as_float(f2tf32(w.x - hi.x));
        hi.y = __uint_as_float(f2tf32(w.y)); lo.y = __uint_as_float(f2tf32(w.y - hi.y));
        hi.z = __uint_as_float(f2tf32(w.z)); lo.z = __uint_as_float(f2tf32(w.z - hi.z));
        hi.w = __uint_as_float(f2tf32(w.w)); lo.w = __uint_as_float(f2tf32(w.w - hi.w));
        *(float4*)(Whi + j * GP + k4) = hi;
        *(float4*)(Wlo + j * GP + k4) = lo;
    }
    int row0 = blk * GM;
    for (int idx = tid; idx < GM * 32; idx += 256) {
        int r = idx >> 5, c = idx & 31;
        int row = row0 + r;
        float4 v = make_float4(0.f, 0.f, 0.f, 0.f);
        if (row < N0) {
            uint2 h = __ldg((const uint2*)S.sin + (long long)row * 32 + c);
            float2 p = __half22float2(*(__half2*)&h.x);
            float2 q = __half22float2(*(__half2*)&h.y);
            v = make_float4(p.x, p.y, q.x, q.y);
        }
        *(float4*)(xs + r * GP + c * 4) = v;
    }
    __syncthreads();

    int warp = tid >> 5, lane = tid & 31;
    int rw = warp * 16 + (lane >> 2);
    int kk = lane & 3;
    float acc[16][4];
    #pragma unroll
    for (int t = 0; t < 16; t++) {
        acc[t][0] = 0.f; acc[t][1] = 0.f; acc[t][2] = 0.f; acc[t][3] = 0.f;
    }

    const float* bhp = Whi + (lane >> 2) * GP + kk;
    const float* blp = Wlo + (lane >> 2) * GP + kk;

    #pragma unroll 1
    for (int ks = 0; ks < 16; ks++) {
        int k0 = ks * 8;
        // x values are fp16-exact in tf32 -> raw fp32 bits are valid tf32 operands
        uint32_t a[4];
        a[0] = __float_as_uint(xs[rw * GP + k0 + kk]);
        a[1] = __float_as_uint(xs[(rw + 8) * GP + k0 + kk]);
        a[2] = __float_as_uint(xs[rw * GP + k0 + kk + 4]);
        a[3] = __float_as_uint(xs[(rw + 8) * GP + k0 + kk + 4]);
        #pragma unroll
        for (int t = 0; t < 16; t++) {
            int off = t * 8 * GP + k0;
            uint32_t bh0 = __float_as_uint(bhp[off]);
            uint32_t bh1 = __float_as_uint(bhp[off + 4]);
            uint32_t bl0 = __float_as_uint(blp[off]);
            uint32_t bl1 = __float_as_uint(blp[off + 4]);
            mma_tf32(acc[t], a, bh0, bh1);
            mma_tf32(acc[t], a, bl0, bl1);
        }
    }

    int jb = 2 * (lane & 3);
    int rg = row0 + warp * 16 + (lane >> 2);
    #pragma unroll
    for (int t = 0; t < 16; t++) {
        int j = t * 8 + jb;
        float2 bb = __ldg((const float2*)(S.b + j));
        if (rg < N0) {
            float2 o;
            o.x = fmaxf(acc[t][0] + bb.x, 0.f);
            o.y = fmaxf(acc[t][1] + bb.y, 0.f);
            *(float2*)(S.obase + (long long)rg * (5 * DD) + j) = o;
        }
        if (rg + 8 < N0) {
            float2 o;
            o.x = fmaxf(acc[t][2] + bb.x, 0.f);
            o.y = fmaxf(acc[t][3] + bb.y, 0.f);
            *(float2*)(S.obase + (long long)(rg + 8) * (5 * DD) + j) = o;
        }
    }
}

// ---------------- attention combine ----------------
__global__ void k_att(const float* __restrict__ attv, float* __restrict__ out) {
    int gt = blockIdx.x * blockDim.x + threadIdx.x;
    int n = gt >> 5;
    int lane = gt & 31;
    if (n >= N0) return;
    const float4* base = (const float4*)(g_allm + (long long)n * (5 * DD));
    float4 a[5];
    float sc[5];
    #pragma unroll
    for (int p = 0; p < 5; p++) {
        a[p] = base[p * 32 + lane];
        float4 av = __ldg((const float4*)attv + p * 32 + lane);
        float d = a[p].x * av.x + a[p].y * av.y + a[p].z * av.z + a[p].w * av.w;
        #pragma unroll
        for (int o = 16; o; o >>= 1) d += __shfl_xor_sync(0xFFFFFFFFu, d, o);
        sc[p] = d;
    }
    float m = sc[0];
    #pragma unroll
    for (int p = 1; p < 5; p++) m = fmaxf(m, sc[p]);
    float ssum = 0.f;
    #pragma unroll
    for (int p = 0; p < 5; p++) { sc[p] = __expf(sc[p] - m); ssum += sc[p]; }
    float inv = 1.0f / ssum;
    float4 o = make_float4(0.f, 0.f, 0.f, 0.f);
    #pragma unroll
    for (int p = 0; p < 5; p++) {
        float wgt = sc[p] * inv;
        o.x += wgt * a[p].x; o.y += wgt * a[p].y;
        o.z += wgt * a[p].z; o.w += wgt * a[p].w;
    }
    ((float4*)out)[(long long)n * 32 + lane] = o;
}

// ---------------- host orchestration ----------------
static inline GList mkl(const __half* feat, const int* offs, const int* gi,
                        const float* gw, const float* xm, __half* out,
                        int nrow, int blk0) {
    GList L; L.feat = feat; L.offs = offs; L.gi = gi; L.gw = gw;
    L.xm = xm; L.out = out; L.nrow = nrow; L.blk0 = blk0; return L;
}

extern "C" void kernel_launch(void* const* d_in, const int* in_sizes, int n_in,
                              void* d_out, int out_size) {
    const float* x_node = (const float*)d_in[0];
    const float* x1   = (const float*)d_in[1];
    const float* x2   = (const float*)d_in[2];
    const float* x3   = (const float*)d_in[3];
    const float* w1   = (const float*)d_in[4];
    const float* w2   = (const float*)d_in[5];
    const float* w3   = (const float*)d_in[6];
    const float* W1   = (const float*)d_in[7];
    const float* b1   = (const float*)d_in[8];
    const float* W2   = (const float*)d_in[9];
    const float* b2   = (const float*)d_in[10];
    const float* W3   = (const float*)d_in[11];
    const float* b3   = (const float*)d_in[12];
    const float* W121 = (const float*)d_in[13];
    const float* b121 = (const float*)d_in[14];
    const float* W131 = (const float*)d_in[15];
    const float* b131 = (const float*)d_in[16];
    const float* attv = (const float*)d_in[17];
    const int* e1s  = (const int*)d_in[18];
    const int* e1d  = (const int*)d_in[19];
    const int* e2s  = (const int*)d_in[20];
    const int* e2d  = (const int*)d_in[21];
    const int* e3s  = (const int*)d_in[22];
    const int* e3d  = (const int*)d_in[23];
    const int* e12s = (const int*)d_in[24];
    const int* e12d = (const int*)d_in[25];
    const int* e13s = (const int*)d_in[26];
    const int* e13d = (const int*)d_in[27];
    float* out = (float*)d_out;

    __half *xn16, *net1, *midB, *midC, *midD, *n3bD, *midE, *n3bE;
    __half *sumA, *sumB, *sumC, *sumD, *sumE;
    float *allm, *gw;
    int *cnt, *offs, *gi;
    cudaGetSymbolAddress((void**)&xn16, g_xn16);
    cudaGetSymbolAddress((void**)&net1, g_net1);
    cudaGetSymbolAddress((void**)&midB, g_midB);
    cudaGetSymbolAddress((void**)&midC, g_midC);
    cudaGetSymbolAddress((void**)&midD, g_midD);
    cudaGetSymbolAddress((void**)&n3bD, g_n3bD);
    cudaGetSymbolAddress((void**)&midE, g_midE);
    cudaGetSymbolAddress((void**)&n3bE, g_n3bE);
    cudaGetSymbolAddress((void**)&sumA, g_sumA);
    cudaGetSymbolAddress((void**)&sumB, g_sumB);
    cudaGetSymbolAddress((void**)&sumC, g_sumC);
    cudaGetSymbolAddress((void**)&sumD, g_sumD);
    cudaGetSymbolAddress((void**)&sumE, g_sumE);
    cudaGetSymbolAddress((void**)&allm, g_allm);
    cudaGetSymbolAddress((void**)&cnt,  g_cnt);
    cudaGetSymbolAddress((void**)&offs, g_offs);
    cudaGetSymbolAddress((void**)&gi,   g_gi);
    cudaGetSymbolAddress((void**)&gw,   g_gw);

    cudaFuncSetAttribute(k_gemm_tf32, cudaFuncAttributeMaxDynamicSharedMemorySize,
                         GEMM_SM_BYTES);

    static cudaStream_t s1 = nullptr;
    static cudaEvent_t evW1, evS1;
    if (!s1) {
        cudaStreamCreateWithFlags(&s1, cudaStreamNonBlocking);
        cudaEventCreateWithFlags(&evW1, cudaEventDisableTiming);
        cudaEventCreateWithFlags(&evS1, cudaEventDisableTiming);
    }

    const int T  = 256;
    const int EB = (NE + T - 1) / T;
    const int BM = (NM + 7) / 8;
    const int BN = (N0 + 7) / 8;

    // ================= CSR build + convert (stream 0) =================
    cudaMemsetAsync(cnt, 0, TOTC * sizeof(int), 0);
    k_cvt<<<(N0 * 32 + T - 1) / T, T>>>(x_node, xn16);
    k_count<<<EB, T>>>(e1s, e1d, e2s, e2d, e3s, e3d, e12s, e12d, e13s, e13d);
    k_scan<<<10, 1024>>>();
    k_fill_all<<<EB, T>>>(e1s, e1d, e2s, e2d, e3s, e3d, e12s, e12d, e13s, e13d,
                          w1, w2, w3);

    // ===== Wave 1 (s0): first hops from xn16 -> net1, midB, midC =====
    {
        GArgs ga; ga.nlists = 3;
        ga.l[0] = mkl(xn16, offs + OB_E1D, gi + GI_E1D, gw + GW_E1D, x1, net1, NM, 0);
        ga.l[1] = mkl(xn16, offs + OB_E2D, gi + GI_E2D, gw + GW_E2D, x2, midB, NM, BM);
        ga.l[2] = mkl(xn16, offs + OB_E3D, gi + GI_E3D, gw + GW_E3D, x3, midC, NM, 2 * BM);
        k_gather16<true, true><<<3 * BM, T>>>(ga);
    }
    cudaEventRecord(evW1, 0);

    // ===== s1: short paths 2,3 second hop + GEMMs =====
    cudaStreamWaitEvent(s1, evW1, 0);
    {
        GArgs ga; ga.nlists = 2;
        ga.l[0] = mkl(midB, offs + OB_E2S, gi + GI_E2S, nullptr, nullptr, sumB, N0, 0);
        ga.l[1] = mkl(midC, offs + OB_E3S, gi + GI_E3S, nullptr, nullptr, sumC, N0, BN);
        k_gather16<false, false><<<2 * BN, T, 0, s1>>>(ga);
    }
    {
        GemmArgs gg;
        gg.s[0] = {sumB, W2, b2, allm + 1 * DD};
        gg.s[1] = {sumC, W3, b3, allm + 2 * DD};
        gg.s[2] = {sumB, W2, b2, allm + 1 * DD};  // unused (grid covers 2 segs)
        k_gemm_tf32<<<2 * GEMM_BLK, T, GEMM_SM_BYTES, s1>>>(gg);
    }
    cudaEventRecord(evS1, s1);

    // ===== s0: long paths hop2, hop3, fused hop4 =====
    {
        GArgs ga; ga.nlists = 2;
        ga.l[0] = mkl(net1, offs + OB_E12D, gi + GI_E12D, nullptr, x2, midD, NM, 0);
        ga.l[1] = mkl(net1, offs + OB_E13D, gi + GI_E13D, nullptr, x3, midE, NM, BM);
        k_gather16<false, true><<<2 * BM, T>>>(ga);
    }
    {
        GArgs ga; ga.nlists = 2;
        ga.l[0] = mkl(midD, offs + OB_E12S, gi + GI_E12S, nullptr, x1, n3bD, NM, 0);
        ga.l[1] = mkl(midE, offs + OB_E13S, gi + GI_E13S, nullptr, x1, n3bE, NM, BM);
        k_gather16<false, true><<<2 * BM, T>>>(ga);
    }
    k_hop4<<<BN, T>>>(net1, n3bD, n3bE, offs + OB_E1S, gi + GI_E1S, gw + GW_E1S,
                      sumA, sumD, sumE);
    {
        GemmArgs gg;
        gg.s[0] = {sumA, W1, b1, allm + 0 * DD};
        gg.s[1] = {sumD, W121, b121, allm + 3 * DD};
        gg.s[2] = {sumE, W131, b131, allm + 4 * DD};
        k_gemm_tf32<<<3 * GEMM_BLK, T, GEMM_SM_BYTES>>>(gg);
    }

    // join + attention combine
    cudaStreamWaitEvent(0, evS1, 0);
    k_att<<<(N0 + 7) / 8, T>>>(attv, out);
}

// round 7
// speedup vs baseline: 2.0410x; 1.0538x over previous
#include <cuda_runtime.h>
#include <cuda_fp16.h>
#include <cstdint>

#define N0   50000
#define NM   25000
#define DD   128
#define NE   800000
#define NE12 400000

// ---------------- counter / offset layout (10 lists, old numbering) ----------------
#define B_E1D  0
#define B_E1S  (B_E1D + NM)
#define B_E2D  (B_E1S + N0)
#define B_E2S  (B_E2D + NM)
#define B_E3D  (B_E2S + N0)
#define B_E3S  (B_E3D + NM)
#define B_E12D (B_E3S + N0)
#define B_E12S (B_E12D + NM)
#define B_E13D (B_E12S + NM)
#define B_E13S (B_E13D + NM)
#define TOTC   (B_E13S + NM)

#define OB_E1D  0
#define OB_E1S  (OB_E1D + NM + 1)
#define OB_E2D  (OB_E1S + N0 + 1)
#define OB_E2S  (OB_E2D + NM + 1)
#define OB_E3D  (OB_E2S + N0 + 1)
#define OB_E3S  (OB_E3D + NM + 1)
#define OB_E12D (OB_E3S + N0 + 1)
#define OB_E12S (OB_E12D + NM + 1)
#define OB_E13D (OB_E12S + NM + 1)
#define OB_E13S (OB_E13D + NM + 1)
#define TOTO    (OB_E13S + NM + 1)

// weighted lists: int2 {idx, w_bits}
#define W_E1D  0
#define W_E1S  (1 * NE)
#define W_E2D  (2 * NE)
#define W_E3D  (3 * NE)
#define TOTW   (4 * NE)
// unweighted lists: int idx
#define U_E2S  0
#define U_E3S  (NE)
#define U_E12D (2 * NE)
#define U_E12S (2 * NE + 1 * NE12)
#define U_E13D (2 * NE + 2 * NE12)
#define U_E13S (2 * NE + 3 * NE12)
#define TOTU   (2 * NE + 4 * NE12)

// ---------------- static device scratch ----------------
__device__ int    g_cnt[TOTC];
__device__ int    g_cur[TOTC];
__device__ int    g_offs[TOTO];
__device__ int2   g_giw[TOTW];
__device__ int    g_gi[TOTU];

__device__ __half g_xn16[(long long)N0 * DD];
__device__ __half g_net1[NM * DD];
__device__ __half g_midB[NM * DD];
__device__ __half g_midC[NM * DD];
__device__ __half g_midD[NM * DD];
__device__ __half g_n3bD[NM * DD];
__device__ __half g_midE[NM * DD];
__device__ __half g_n3bE[NM * DD];
__device__ __half g_sumA[(long long)N0 * DD];
__device__ __half g_sumB[(long long)N0 * DD];
__device__ __half g_sumC[(long long)N0 * DD];
__device__ __half g_sumD[(long long)N0 * DD];
__device__ __half g_sumE[(long long)N0 * DD];
__device__ float  g_allm[(long long)N0 * 5 * DD];

__constant__ int c_lbase[10] = {B_E1D,B_E1S,B_E2D,B_E2S,B_E3D,B_E3S,B_E12D,B_E12S,B_E13D,B_E13S};
__constant__ int c_obase[10] = {OB_E1D,OB_E1S,OB_E2D,OB_E2S,OB_E3D,OB_E3S,OB_E12D,OB_E12S,OB_E13D,OB_E13S};
__constant__ int c_ln[10]    = {NM,N0,NM,N0,NM,N0,NM,NM,NM,NM};
// scan order: chain A = {E1D,E2D,E3D} then chain B = rest
__constant__ int c_order[10] = {0,2,4, 1,3,5,6,7,8,9};

// ---------------- fp16 helpers ----------------
__device__ __forceinline__ void acc4w(float4& a, uint2 v, float w) {
    float2 p = __half22float2(*(__half2*)&v.x);
    float2 q = __half22float2(*(__half2*)&v.y);
    a.x += p.x * w; a.y += p.y * w; a.z += q.x * w; a.w += q.y * w;
}
__device__ __forceinline__ void acc4(float4& a, uint2 v) {
    float2 p = __half22float2(*(__half2*)&v.x);
    float2 q = __half22float2(*(__half2*)&v.y);
    a.x += p.x; a.y += p.y; a.z += q.x; a.w += q.y;
}
__device__ __forceinline__ uint2 pack4(float4 a) {
    __half2 h0 = __floats2half2_rn(a.x, a.y);
    __half2 h1 = __floats2half2_rn(a.z, a.w);
    uint2 r; r.x = *(unsigned*)&h0; r.y = *(unsigned*)&h1; return r;
}

// ---------------- CSR build (two chains) ----------------
__global__ void k_countA(const int* __restrict__ e1d, const int* __restrict__ e2d,
                         const int* __restrict__ e3d) {
    int i = blockIdx.x * blockDim.x + threadIdx.x;
    if (i >= NE) return;
    atomicAdd(&g_cnt[B_E1D + e1d[i]], 1);
    atomicAdd(&g_cnt[B_E2D + e2d[i]], 1);
    atomicAdd(&g_cnt[B_E3D + e3d[i]], 1);
}

__global__ void k_countB(const int* __restrict__ e1s, const int* __restrict__ e2s,
                         const int* __restrict__ e3s,
                         const int* __restrict__ e12s, const int* __restrict__ e12d,
                         const int* __restrict__ e13s, const int* __restrict__ e13d) {
    int i = blockIdx.x * blockDim.x + threadIdx.x;
    if (i < NE) {
        atomicAdd(&g_cnt[B_E1S + e1s[i]], 1);
        atomicAdd(&g_cnt[B_E2S + e2s[i]], 1);
        atomicAdd(&g_cnt[B_E3S + e3s[i]], 1);
    }
    if (i < NE12) {
        atomicAdd(&g_cnt[B_E12D + e12d[i]], 1); atomicAdd(&g_cnt[B_E12S + e12s[i]], 1);
        atomicAdd(&g_cnt[B_E13D + e13d[i]], 1); atomicAdd(&g_cnt[B_E13S + e13s[i]], 1);
    }
}

// one block per list (selected via c_order[ord0 + blockIdx.x])
__global__ void k_scan(int ord0) {
    __shared__ int sh[1024];
    int b = c_order[ord0 + blockIdx.x];
    int n  = c_ln[b];
    int cb = c_lbase[b];
    int ob = c_obase[b];
    int t = threadIdx.x;
    int chunk = (n + 1023) >> 10;
    int lo = t * chunk;
    int hi = lo + chunk; if (hi > n) hi = n; if (lo > n) lo = n;
    int s = 0;
    for (int i = lo; i < hi; i++) s += g_cnt[cb + i];
    sh[t] = s;
    __syncthreads();
    for (int d = 1; d < 1024; d <<= 1) {
        int v = (t >= d) ? sh[t - d] : 0;
        __syncthreads();
        sh[t] += v;
        __syncthreads();
    }
    int run = (t == 0) ? 0 : sh[t - 1];
    for (int i = lo; i < hi; i++) {
        g_offs[ob + i] = run;
        g_cur [cb + i] = run;
        run += g_cnt[cb + i];
    }
    if (t == 1023) g_offs[ob + n] = sh[1023];
}

__global__ void k_fillA(const int* __restrict__ e1s, const int* __restrict__ e1d,
                        const int* __restrict__ e2s, const int* __restrict__ e2d,
                        const int* __restrict__ e3s, const int* __restrict__ e3d,
                        const float* __restrict__ w1, const float* __restrict__ w2,
                        const float* __restrict__ w3) {
    int e = blockIdx.x * blockDim.x + threadIdx.x;
    if (e >= NE) return;
    int a1 = __ldg(e1s + e), b1 = __ldg(e1d + e); int ww1 = __ldg((const int*)w1 + e);
    int a2 = __ldg(e2s + e), b2 = __ldg(e2d + e); int ww2 = __ldg((const int*)w2 + e);
    int a3 = __ldg(e3s + e), b3 = __ldg(e3d + e); int ww3 = __ldg((const int*)w3 + e);
    int p0 = atomicAdd(&g_cur[B_E1D + b1], 1);
    int p1 = atomicAdd(&g_cur[B_E2D + b2], 1);
    int p2 = atomicAdd(&g_cur[B_E3D + b3], 1);
    g_giw[W_E1D + p0] = make_int2(a1, ww1);
    g_giw[W_E2D + p1] = make_int2(a2, ww2);
    g_giw[W_E3D + p2] = make_int2(a3, ww3);
}

__global__ void k_fillB(const int* __restrict__ e1s, const int* __restrict__ e1d,
                        const int* __restrict__ e2s, const int* __restrict__ e2d,
                        const int* __restrict__ e3s, const int* __restrict__ e3d,
                        const int* __restrict__ e12s, const int* __restrict__ e12d,
                        const int* __restrict__ e13s, const int* __restrict__ e13d,
                        const float* __restrict__ w1) {
    int e = blockIdx.x * blockDim.x + threadIdx.x;
    if (e < NE) {
        int a1 = __ldg(e1s + e), b1 = __ldg(e1d + e); int ww1 = __ldg((const int*)w1 + e);
        int a2 = __ldg(e2s + e), b2 = __ldg(e2d + e);
        int a3 = __ldg(e3s + e), b3 = __ldg(e3d + e);
        int p0 = atomicAdd(&g_cur[B_E1S + a1], 1);
        int p1 = atomicAdd(&g_cur[B_E2S + a2], 1);
        int p2 = atomicAdd(&g_cur[B_E3S + a3], 1);
        g_giw[W_E1S + p0] = make_int2(b1, ww1);
        g_gi[U_E2S + p1] = b2;
        g_gi[U_E3S + p2] = b3;
    }
    if (e < NE12) {
        int a4 = __ldg(e12s + e), b4 = __ldg(e12d + e);
        int a5 = __ldg(e13s + e), b5 = __ldg(e13d + e);
        int p3 = atomicAdd(&g_cur[B_E12D + b4], 1);
        int p4 = atomicAdd(&g_cur[B_E12S + a4], 1);
        int p5 = atomicAdd(&g_cur[B_E13D + b5], 1);
        int p6 = atomicAdd(&g_cur[B_E13S + a5], 1);
        g_gi[U_E12D + p3] = a4;
        g_gi[U_E12S + p4] = b4;
        g_gi[U_E13D + p5] = a5;
        g_gi[U_E13S + p6] = b5;
    }
}

// ---------------- x_node fp32 -> fp16 ----------------
__global__ void k_cvt(const float* __restrict__ x, __half* __restrict__ y) {
    int i = blockIdx.x * blockDim.x + threadIdx.x;
    if (i >= N0 * 32) return;
    float4 v = __ldg((const float4*)x + i);
    ((uint2*)y)[i] = pack4(v);
}

// ---------------- mega gathers (fp16 rows) ----------------
struct GList {
    const __half* feat;
    const int*    offs;
    const void*   gidx;   // int2 (weighted) or int (unweighted)
    const float*  xm;     // fp32, null -> no combine
    __half*       out;
    int           nrow;
    int           blk0;
};
struct GArgs { GList l[4]; int nlists; };

template<bool HASW, bool COMBINE>
__global__ void __launch_bounds__(256) k_gather16(GArgs ga) {
    int li = 0;
    #pragma unroll
    for (int i = 1; i < 4; i++)
        if (i < ga.nlists && (int)blockIdx.x >= ga.l[i].blk0) li = i;
    const GList& L = ga.l[li];

    int n = (blockIdx.x - L.blk0) * 8 + (threadIdx.x >> 5);
    int lane = threadIdx.x & 31;
    if (n >= L.nrow) return;

    const uint2* feat = (const uint2*)L.feat;
    const int2*  giw  = (const int2*)L.gidx;
    const int*   gi   = (const int*)L.gidx;
    int beg = __ldg(L.offs + n);
    int end = __ldg(L.offs + n + 1);

    float4 a0 = make_float4(0.f, 0.f, 0.f, 0.f);
    float4 a1 = a0;
    int e = beg;
    for (; e + 8 <= end; e += 8) {
        if (HASW) {
            int2 p0 = __ldg(giw + e + 0), p1 = __ldg(giw + e + 1);
            int2 p2 = __ldg(giw + e + 2), p3 = __ldg(giw + e + 3);
            int2 p4 = __ldg(giw + e + 4), p5 = __ldg(giw + e + 5);
            int2 p6 = __ldg(giw + e + 6), p7 = __ldg(giw + e + 7);
            uint2 v0 = __ldg(feat + ((unsigned)p0.x << 5) + lane);
            uint2 v1 = __ldg(feat + ((unsigned)p1.x << 5) + lane);
            uint2 v2 = __ldg(feat + ((unsigned)p2.x << 5) + lane);
            uint2 v3 = __ldg(feat + ((unsigned)p3.x << 5) + lane);
            uint2 v4 = __ldg(feat + ((unsigned)p4.x << 5) + lane);
            uint2 v5 = __ldg(feat + ((unsigned)p5.x << 5) + lane);
            uint2 v6 = __ldg(feat + ((unsigned)p6.x << 5) + lane);
            uint2 v7 = __ldg(feat + ((unsigned)p7.x << 5) + lane);
            acc4w(a0, v0, __int_as_float(p0.y)); acc4w(a1, v1, __int_as_float(p1.y));
            acc4w(a0, v2, __int_as_float(p2.y)); acc4w(a1, v3, __int_as_float(p3.y));
            acc4w(a0, v4, __int_as_float(p4.y)); acc4w(a1, v5, __int_as_float(p5.y));
            acc4w(a0, v6, __int_as_float(p6.y)); acc4w(a1, v7, __int_as_float(p7.y));
        } else {
            int g0 = __ldg(gi + e + 0), g1 = __ldg(gi + e + 1);
            int g2 = __ldg(gi + e + 2), g3 = __ldg(gi + e + 3);
            int g4 = __ldg(gi + e + 4), g5 = __ldg(gi + e + 5);
            int g6 = __ldg(gi + e + 6), g7 = __ldg(gi + e + 7);
            uint2 v0 = __ldg(feat + ((unsigned)g0 << 5) + lane);
            uint2 v1 = __ldg(feat + ((unsigned)g1 << 5) + lane);
            uint2 v2 = __ldg(feat + ((unsigned)g2 << 5) + lane);
            uint2 v3 = __ldg(feat + ((unsigned)g3 << 5) + lane);
            uint2 v4 = __ldg(feat + ((unsigned)g4 << 5) + lane);
            uint2 v5 = __ldg(feat + ((unsigned)g5 << 5) + lane);
            uint2 v6 = __ldg(feat + ((unsigned)g6 << 5) + lane);
            uint2 v7 = __ldg(feat + ((unsigned)g7 << 5) + lane);
            acc4(a0, v0); acc4(a1, v1); acc4(a0, v2); acc4(a1, v3);
            acc4(a0, v4); acc4(a1, v5); acc4(a0, v6); acc4(a1, v7);
        }
    }
    for (; e < end; e++) {
        if (HASW) {
            int2 p = __ldg(giw + e);
            uint2 v = __ldg(feat + ((unsigned)p.x << 5) + lane);
            acc4w(a0, v, __int_as_float(p.y));
        } else {
            int g = __ldg(gi + e);
            uint2 v = __ldg(feat + ((unsigned)g << 5) + lane);
            acc4(a0, v);
        }
    }
    float4 acc;
    acc.x = a0.x + a1.x; acc.y = a0.y + a1.y;
    acc.z = a0.z + a1.z; acc.w = a0.w + a1.w;
    int deg = end - beg;
    float r = 1.0f / (float)(deg < 1 ? 1 : deg);
    acc.x *= r; acc.y *= r; acc.z *= r; acc.w *= r;
    if (COMBINE) {
        float4 x = __ldg((const float4*)L.xm + n * 32 + lane);
        acc.x = (acc.x + x.x) * 0.5f;
        acc.y = (acc.y + x.y) * 0.5f;
        acc.z = (acc.z + x.z) * 0.5f;
        acc.w = (acc.w + x.w) * 0.5f;
    }
    ((uint2*)L.out)[n * 32 + lane] = pack4(acc);
}

// ---------------- fused hop4: one E1S walk (int2), 3 fp16 sources -> 3 fp16 sums ----------------
__global__ void __launch_bounds__(256) k_hop4(const __half* __restrict__ fA,
                                              const __half* __restrict__ fD,
                                              const __half* __restrict__ fE,
                                              const int* __restrict__ offs,
                                              const int2* __restrict__ giw,
                                              __half* __restrict__ sA,
                                              __half* __restrict__ sD,
                                              __half* __restrict__ sE) {
    int n = blockIdx.x * 8 + (threadIdx.x >> 5);
    int lane = threadIdx.x & 31;
    if (n >= N0) return;
    int beg = __ldg(offs + n);
    int end = __ldg(offs + n + 1);
    const uint2* A = (const uint2*)fA;
    const uint2* D = (const uint2*)fD;
    const uint2* E = (const uint2*)fE;
    float4 aA = make_float4(0.f,0.f,0.f,0.f), aD = aA, aE = aA;
    int e = beg;
    for (; e + 4 <= end; e += 4) {
        int2 p0 = __ldg(giw + e + 0), p1 = __ldg(giw + e + 1);
        int2 p2 = __ldg(giw + e + 2), p3 = __ldg(giw + e + 3);
        float w0 = __int_as_float(p0.y), w1 = __int_as_float(p1.y);
        float w2 = __int_as_float(p2.y), w3 = __int_as_float(p3.y);
        unsigned o0 = ((unsigned)p0.x << 5) + lane;
        unsigned o1 = ((unsigned)p1.x << 5) + lane;
        unsigned o2 = ((unsigned)p2.x << 5) + lane;
        unsigned o3 = ((unsigned)p3.x << 5) + lane;
        uint2 vA0 = __ldg(A + o0), vA1 = __ldg(A + o1), vA2 = __ldg(A + o2), vA3 = __ldg(A + o3);
        uint2 vD0 = __ldg(D + o0), vD1 = __ldg(D + o1), vD2 = __ldg(D + o2), vD3 = __ldg(D + o3);
        uint2 vE0 = __ldg(E + o0), vE1 = __ldg(E + o1), vE2 = __ldg(E + o2), vE3 = __ldg(E + o3);
        acc4(aA, vA0); acc4(aA, vA1); acc4(aA, vA2); acc4(aA, vA3);
        acc4w(aD, vD0, w0); acc4w(aD, vD1, w1); acc4w(aD, vD2, w2); acc4w(aD, vD3, w3);
        acc4w(aE, vE0, w0); acc4w(aE, vE1, w1); acc4w(aE, vE2, w2); acc4w(aE, vE3, w3);
    }
    for (; e < end; e++) {
        int2 p = __ldg(giw + e);
        float w = __int_as_float(p.y);
        unsigned o = ((unsigned)p.x << 5) + lane;
        acc4(aA, __ldg(A + o));
        acc4w(aD, __ldg(D + o), w);
        acc4w(aE, __ldg(E + o), w);
    }
    int deg = end - beg;
    float r = 1.0f / (float)(deg < 1 ? 1 : deg);
    aA.x *= r; aA.y *= r; aA.z *= r; aA.w *= r;
    aD.x *= r; aD.y *= r; aD.z *= r; aD.w *= r;
    aE.x *= r; aE.y *= r; aE.z *= r; aE.w *= r;
    unsigned oi = n * 32 + lane;
    ((uint2*)sA)[oi] = pack4(aA);
    ((uint2*)sD)[oi] = pack4(aD);
    ((uint2*)sE)[oi] = pack4(aE);
}

// ---------------- tf32 tensor-core GEMM + bias + relu (fp16 input) ----------------
#define GM   128
#define GP   132
#define GEMM_BLK ((N0 + GM - 1) / GM)
#define GEMM_SM_BYTES (3 * GM * GP * 4)

struct GemmSeg { const __half* sin; const float* W; const float* b; float* obase; };
struct GemmArgs { GemmSeg s[3]; };

__device__ __forceinline__ uint32_t f2tf32(float x) {
    uint32_t r;
    asm("cvt.rna.tf32.f32 %0, %1;" : "=r"(r) : "f"(x));
    return r;
}

__device__ __forceinline__ void mma_tf32(float* c, const uint32_t* a,
                                         uint32_t b0, uint32_t b1) {
    asm("mma.sync.aligned.m16n8k8.row.col.f32.tf32.tf32.f32 "
        "{%0,%1,%2,%3}, {%4,%5,%6,%7}, {%8,%9}, {%0,%1,%2,%3};"
        : "+f"(c[0]), "+f"(c[1]), "+f"(c[2]), "+f"(c[3])
        : "r"(a[0]), "r"(a[1]), "r"(a[2]), "r"(a[3]), "r"(b0), "r"(b1));
}

__global__ void __launch_bounds__(256) k_gemm_tf32(GemmArgs gargs) {
    extern __shared__ float sh[];
    float* Whi = sh;
    float* Wlo = sh + GM * GP;
    float* xs  = sh + 2 * GM * GP;
    int tid = threadIdx.x;
    int seg = blockIdx.x / GEMM_BLK;
    int blk = blockIdx.x % GEMM_BLK;
    const GemmSeg S = gargs.s[seg];

    for (int idx = tid; idx < DD * DD / 4; idx += 256) {
        int j = idx >> 5, k4 = (idx & 31) * 4;
        float4 w = __ldg((const float4*)S.W + idx);
        float4 hi, lo;
        hi.x = __uint_as_float(f2tf32(w.x)); lo.x = __uint_as_float(f2tf32(w.x - hi.x));
        hi.y = __uint_as_float(f2tf32(w.y)); lo.y = __uint_as_float(f2tf32(w.y - hi.y));
        hi.z = __uint_as_float(f2tf32(w.z)); lo.z = __uint_as_float(f2tf32(w.z - hi.z));
        hi.w = __uint_as_float(f2tf32(w.w)); lo.w = __uint_as_float(f2tf32(w.w - hi.w));
        *(float4*)(Whi + j * GP + k4) = hi;
        *(float4*)(Wlo + j * GP + k4) = lo;
    }
    int row0 = blk * GM;
    for (int idx = tid; idx < GM * 32; idx += 256) {
        int r = idx >> 5, c = idx & 31;
        int row = row0 + r;
        float4 v = make_float4(0.f, 0.f, 0.f, 0.f);
        if (row < N0) {
            uint2 h = __ldg((const uint2*)S.sin + (long long)row * 32 + c);
            float2 p = __half22float2(*(__half2*)&h.x);
            float2 q = __half22float2(*(__half2*)&h.y);
            v = make_float4(p.x, p.y, q.x, q.y);
        }
        *(float4*)(xs + r * GP + c * 4) = v;
    }
    __syncthreads();

    int warp = tid >> 5, lane = tid & 31;
    int rw = warp * 16 + (lane >> 2);
    int kk = lane & 3;
    float acc[16][4];
    #pragma unroll
    for (int t = 0; t < 16; t++) {
        acc[t][0] = 0.f; acc[t][1] = 0.f; acc[t][2] = 0.f; acc[t][3] = 0.f;
    }

    const float* bhp = Whi + (lane >> 2) * GP + kk;
    const float* blp = Wlo + (lane >> 2) * GP + kk;

    #pragma unroll 1
    for (int ks = 0; ks < 16; ks++) {
        int k0 = ks * 8;
        uint32_t a[4];
        a[0] = __float_as_uint(xs[rw * GP + k0 + kk]);
        a[1] = __float_as_uint(xs[(rw + 8) * GP + k0 + kk]);
        a[2] = __float_as_uint(xs[rw * GP + k0 + kk + 4]);
        a[3] = __float_as_uint(xs[(rw + 8) * GP + k0 + kk + 4]);
        #pragma unroll
        for (int t = 0; t < 16; t++) {
            int off = t * 8 * GP + k0;
            uint32_t bh0 = __float_as_uint(bhp[off]);
            uint32_t bh1 = __float_as_uint(bhp[off + 4]);
            uint32_t bl0 = __float_as_uint(blp[off]);
            uint32_t bl1 = __float_as_uint(blp[off + 4]);
            mma_tf32(acc[t], a, bh0, bh1);
            mma_tf32(acc[t], a, bl0, bl1);
        }
    }

    int jb = 2 * (lane & 3);
    int rg = row0 + warp * 16 + (lane >> 2);
    #pragma unroll
    for (int t = 0; t < 16; t++) {
        int j = t * 8 + jb;
        float2 bb = __ldg((const float2*)(S.b + j));
        if (rg < N0) {
            float2 o;
            o.x = fmaxf(acc[t][0] + bb.x, 0.f);
            o.y = fmaxf(acc[t][1] + bb.y, 0.f);
            *(float2*)(S.obase + (long long)rg * (5 * DD) + j) = o;
        }
        if (rg + 8 < N0) {
            float2 o;
            o.x = fmaxf(acc[t][2] + bb.x, 0.f);
            o.y = fmaxf(acc[t][3] + bb.y, 0.f);
            *(float2*)(S.obase + (long long)(rg + 8) * (5 * DD) + j) = o;
        }
    }
}

// ---------------- attention combine ----------------
__global__ void k_att(const float* __restrict__ attv, float* __restrict__ out) {
    int gt = blockIdx.x * blockDim.x + threadIdx.x;
    int n = gt >> 5;
    int lane = gt & 31;
    if (n >= N0) return;
    const float4* base = (const float4*)(g_allm + (long long)n * (5 * DD));
    float4 a[5];
    float sc[5];
    #pragma unroll
    for (int p = 0; p < 5; p++) {
        a[p] = base[p * 32 + lane];
        float4 av = __ldg((const float4*)attv + p * 32 + lane);
        float d = a[p].x * av.x + a[p].y * av.y + a[p].z * av.z + a[p].w * av.w;
        #pragma unroll
        for (int o = 16; o; o >>= 1) d += __shfl_xor_sync(0xFFFFFFFFu, d, o);
        sc[p] = d;
    }
    float m = sc[0];
    #pragma unroll
    for (int p = 1; p < 5; p++) m = fmaxf(m, sc[p]);
    float ssum = 0.f;
    #pragma unroll
    for (int p = 0; p < 5; p++) { sc[p] = __expf(sc[p] - m); ssum += sc[p]; }
    float inv = 1.0f / ssum;
    float4 o = make_float4(0.f, 0.f, 0.f, 0.f);
    #pragma unroll
    for (int p = 0; p < 5; p++) {
        float wgt = sc[p] * inv;
        o.x += wgt * a[p].x; o.y += wgt * a[p].y;
        o.z += wgt * a[p].z; o.w += wgt * a[p].w;
    }
    ((float4*)out)[(long long)n * 32 + lane] = o;
}

// ---------------- host orchestration ----------------
static inline GList mkl(const __half* feat, const int* offs, const void* gidx,
                        const float* xm, __half* out, int nrow, int blk0) {
    GList L; L.feat = feat; L.offs = offs; L.gidx = gidx;
    L.xm = xm; L.out = out; L.nrow = nrow; L.blk0 = blk0; return L;
}

extern "C" void kernel_launch(void* const* d_in, const int* in_sizes, int n_in,
                              void* d_out, int out_size) {
    const float* x_node = (const float*)d_in[0];
    const float* x1   = (const float*)d_in[1];
    const float* x2   = (const float*)d_in[2];
    const float* x3   = (const float*)d_in[3];
    const float* w1   = (const float*)d_in[4];
    const float* w2   = (const float*)d_in[5];
    const float* w3   = (const float*)d_in[6];
    const float* W1   = (const float*)d_in[7];
    const float* b1   = (const float*)d_in[8];
    const float* W2   = (const float*)d_in[9];
    const float* b2   = (const float*)d_in[10];
    const float* W3   = (const float*)d_in[11];
    const float* b3   = (const float*)d_in[12];
    const float* W121 = (const float*)d_in[13];
    const float* b121 = (const float*)d_in[14];
    const float* W131 = (const float*)d_in[15];
    const float* b131 = (const float*)d_in[16];
    const float* attv = (const float*)d_in[17];
    const int* e1s  = (const int*)d_in[18];
    const int* e1d  = (const int*)d_in[19];
    const int* e2s  = (const int*)d_in[20];
    const int* e2d  = (const int*)d_in[21];
    const int* e3s  = (const int*)d_in[22];
    const int* e3d  = (const int*)d_in[23];
    const int* e12s = (const int*)d_in[24];
    const int* e12d = (const int*)d_in[25];
    const int* e13s = (const int*)d_in[26];
    const int* e13d = (const int*)d_in[27];
    float* out = (float*)d_out;

    __half *xn16, *net1, *midB, *midC, *midD, *n3bD, *midE, *n3bE;
    __half *sumA, *sumB, *sumC, *sumD, *sumE;
    float *allm;
    int *cnt, *offs, *gi;
    int2 *giw;
    cudaGetSymbolAddress((void**)&xn16, g_xn16);
    cudaGetSymbolAddress((void**)&net1, g_net1);
    cudaGetSymbolAddress((void**)&midB, g_midB);
    cudaGetSymbolAddress((void**)&midC, g_midC);
    cudaGetSymbolAddress((void**)&midD, g_midD);
    cudaGetSymbolAddress((void**)&n3bD, g_n3bD);
    cudaGetSymbolAddress((void**)&midE, g_midE);
    cudaGetSymbolAddress((void**)&n3bE, g_n3bE);
    cudaGetSymbolAddress((void**)&sumA, g_sumA);
    cudaGetSymbolAddress((void**)&sumB, g_sumB);
    cudaGetSymbolAddress((void**)&sumC, g_sumC);
    cudaGetSymbolAddress((void**)&sumD, g_sumD);
    cudaGetSymbolAddress((void**)&sumE, g_sumE);
    cudaGetSymbolAddress((void**)&allm, g_allm);
    cudaGetSymbolAddress((void**)&cnt,  g_cnt);
    cudaGetSymbolAddress((void**)&offs, g_offs);
    cudaGetSymbolAddress((void**)&gi,   g_gi);
    cudaGetSymbolAddress((void**)&giw,  g_giw);

    cudaFuncSetAttribute(k_gemm_tf32, cudaFuncAttributeMaxDynamicSharedMemorySize,
                         GEMM_SM_BYTES);

    static cudaStream_t s1 = nullptr;
    static cudaEvent_t evZ, evW1, evB, evS1;
    if (!s1) {
        cudaStreamCreateWithFlags(&s1, cudaStreamNonBlocking);
        cudaEventCreateWithFlags(&evZ,  cudaEventDisableTiming);
        cudaEventCreateWithFlags(&evW1, cudaEventDisableTiming);
        cudaEventCreateWithFlags(&evB,  cudaEventDisableTiming);
        cudaEventCreateWithFlags(&evS1, cudaEventDisableTiming);
    }

    const int T  = 256;
    const int EB = (NE + T - 1) / T;
    const int BM = (NM + 7) / 8;
    const int BN = (N0 + 7) / 8;

    // ====== s0: zero counters, cvt, chain A (E1D/E2D/E3D) ======
    cudaMemsetAsync(cnt, 0, TOTC * sizeof(int), 0);
    cudaEventRecord(evZ, 0);
    k_cvt<<<(N0 * 32 + T - 1) / T, T>>>(x_node, xn16);
    k_countA<<<EB, T>>>(e1d, e2d, e3d);
    k_scan<<<3, 1024>>>(0);
    k_fillA<<<EB, T>>>(e1s, e1d, e2s, e2d, e3s, e3d, w1, w2, w3);

    // ====== s1: chain B (remaining 7 lists), overlapped ======
    cudaStreamWaitEvent(s1, evZ, 0);
    k_countB<<<EB, T, 0, s1>>>(e1s, e2s, e3s, e12s, e12d, e13s, e13d);
    k_scan<<<7, 1024, 0, s1>>>(3);
    k_fillB<<<EB, T, 0, s1>>>(e1s, e1d, e2s, e2d, e3s, e3d,
                              e12s, e12d, e13s, e13d, w1);
    cudaEventRecord(evB, s1);

    // ====== s0: wave 1 — first hops from xn16 ======
    {
        GArgs ga; ga.nlists = 3;
        ga.l[0] = mkl(xn16, offs + OB_E1D, giw + W_E1D, x1, net1, NM, 0);
        ga.l[1] = mkl(xn16, offs + OB_E2D, giw + W_E2D, x2, midB, NM, BM);
        ga.l[2] = mkl(xn16, offs + OB_E3D, giw + W_E3D, x3, midC, NM, 2 * BM);
        k_gather16<true, true><<<3 * BM, T>>>(ga);
    }
    cudaEventRecord(evW1, 0);

    // ====== s1: short paths 2,3 second hop + GEMMs ======
    cudaStreamWaitEvent(s1, evW1, 0);
    {
        GArgs ga; ga.nlists = 2;
        ga.l[0] = mkl(midB, offs + OB_E2S, gi + U_E2S, nullptr, sumB, N0, 0);
        ga.l[1] = mkl(midC, offs + OB_E3S, gi + U_E3S, nullptr, sumC, N0, BN);
        k_gather16<false, false><<<2 * BN, T, 0, s1>>>(ga);
    }
    {
        GemmArgs gg;
        gg.s[0] = {sumB, W2, b2, allm + 1 * DD};
        gg.s[1] = {sumC, W3, b3, allm + 2 * DD};
        gg.s[2] = {sumB, W2, b2, allm + 1 * DD};  // unused
        k_gemm_tf32<<<2 * GEMM_BLK, T, GEMM_SM_BYTES, s1>>>(gg);
    }
    cudaEventRecord(evS1, s1);

    // ====== s0: long paths (need chain B lists) ======
    cudaStreamWaitEvent(0, evB, 0);
    {
        GArgs ga; ga.nlists = 2;
        ga.l[0] = mkl(net1, offs + OB_E12D, gi + U_E12D, x2, midD, NM, 0);
        ga.l[1] = mkl(net1, offs + OB_E13D, gi + U_E13D, x3, midE, NM, BM);
        k_gather16<false, true><<<2 * BM, T>>>(ga);
    }
    {
        GArgs ga; ga.nlists = 2;
        ga.l[0] = mkl(midD, offs + OB_E12S, gi + U_E12S, x1, n3bD, NM, 0);
        ga.l[1] = mkl(midE, offs + OB_E13S, gi + U_E13S, x1, n3bE, NM, BM);
        k_gather16<false, true><<<2 * BM, T>>>(ga);
    }
    k_hop4<<<BN, T>>>(net1, n3bD, n3bE, offs + OB_E1S, giw + W_E1S,
                      sumA, sumD, sumE);
    {
        GemmArgs gg;
        gg.s[0] = {sumA, W1, b1, allm + 0 * DD};
        gg.s[1] = {sumD, W121, b121, allm + 3 * DD};
        gg.s[2] = {sumE, W131, b131, allm + 4 * DD};
        k_gemm_tf32<<<3 * GEMM_BLK, T, GEMM_SM_BYTES>>>(gg);
    }

    // ====== join + attention ======
    cudaStreamWaitEvent(0, evS1, 0);
    k_att<<<(N0 + 7) / 8, T>>>(attv, out);
}